// round 13
// baseline (speedup 1.0000x reference)
#include <cuda_runtime.h>
#include <cuda_bf16.h>
#include <cstdint>

#define MROWS  4096
#define DMODEL 1024
#define DIN    512
#define NHEAD  16
#define SEQ    2048

// ---------------- scratch (allocation-free) ----------------
__device__ __align__(128) float g_e  [MROWS*DMODEL];
__device__ __align__(128) float g_mha[MROWS*DMODEL];
__device__ __align__(128) __nv_bfloat16 g_xh[MROWS*DIN],    g_xl[MROWS*DIN];
__device__ __align__(128) __nv_bfloat16 g_eh[MROWS*DMODEL], g_el[MROWS*DMODEL];
__device__ __align__(128) __nv_bfloat16 g_qh[MROWS*DMODEL], g_ql[MROWS*DMODEL];
__device__ __align__(128) __nv_bfloat16 g_kh[MROWS*DMODEL], g_kl[MROWS*DMODEL];
__device__ __align__(128) __nv_bfloat16 g_vh[MROWS*DMODEL], g_vl[MROWS*DMODEL];
__device__ __align__(128) __nv_bfloat16 g_ch[MROWS*DMODEL], g_cl[MROWS*DMODEL];
__device__ __align__(128) __nv_bfloat16 g_mh[MROWS*DMODEL], g_ml[MROWS*DMODEL];
__device__ __align__(128) __nv_bfloat16 g_hh[MROWS*DMODEL], g_hl[MROWS*DMODEL];
#define WSZ_E (DMODEL*DIN)
#define WSZ   (DMODEL*DMODEL)
__device__ __align__(128) __nv_bfloat16 g_Wth[WSZ_E + 6*WSZ];
__device__ __align__(128) __nv_bfloat16 g_Wtl[WSZ_E + 6*WSZ];

// ---------------- helpers ----------------
__device__ __forceinline__ uint32_t smem_u32(const void* p) {
    uint32_t a;
    asm("{ .reg .u64 t; cvta.to.shared.u64 t, %1; cvt.u32.u64 %0, t; }" : "=r"(a) : "l"(p));
    return a;
}

#define CP_ASYNC16(dst, src) \
    asm volatile("cp.async.cg.shared.global [%0], [%1], 16;" :: "r"(dst), "l"(src) : "memory")
#define CP_COMMIT()  asm volatile("cp.async.commit_group;" ::: "memory")
#define CP_WAIT1()   asm volatile("cp.async.wait_group 1;" ::: "memory")
#define CP_WAIT0()   asm volatile("cp.async.wait_group 0;" ::: "memory")

#define LDSM4(r0, r1, r2, r3, a) \
    asm volatile("ldmatrix.sync.aligned.m8n8.x4.shared.b16 {%0,%1,%2,%3}, [%4];" \
                 : "=r"(r0), "=r"(r1), "=r"(r2), "=r"(r3) : "r"(a))
#define LDSM4T(r0, r1, r2, r3, a) \
    asm volatile("ldmatrix.sync.aligned.m8n8.x4.trans.shared.b16 {%0,%1,%2,%3}, [%4];" \
                 : "=r"(r0), "=r"(r1), "=r"(r2), "=r"(r3) : "r"(a))

#define MMA16816(d, a, b) \
    asm volatile("mma.sync.aligned.m16n8k16.row.col.f32.bf16.bf16.f32 " \
                 "{%0,%1,%2,%3}, {%4,%5,%6,%7}, {%8,%9}, {%0,%1,%2,%3};" \
                 : "+f"((d)[0]), "+f"((d)[1]), "+f"((d)[2]), "+f"((d)[3]) \
                 : "r"((a)[0]), "r"((a)[1]), "r"((a)[2]), "r"((a)[3]), \
                   "r"((b)[0]), "r"((b)[1]))

__device__ __forceinline__ uint32_t packbf2(float a, float b) {
    __nv_bfloat162 t;
    t.x = __float2bfloat16(a);
    t.y = __float2bfloat16(b);
    return *(uint32_t*)&t;
}

// ============================================================================
// Fused weight transpose + bf16 hi/lo split for all 7 weights (grid.z selects)
// ============================================================================
__global__ void __launch_bounds__(256)
wsplit_all(const float* __restrict__ We, const float* __restrict__ Wq,
           const float* __restrict__ Wk, const float* __restrict__ Wv,
           const float* __restrict__ W0, const float* __restrict__ W1,
           const float* __restrict__ W2,
           __nv_bfloat16* __restrict__ ThB, __nv_bfloat16* __restrict__ TlB)
{
    const int z = blockIdx.z;
    const int K = (z == 0) ? DIN : DMODEL;
    if ((int)blockIdx.y * 32 >= K) return;
    const float* W = (z == 0) ? We : (z == 1) ? Wq : (z == 2) ? Wk :
                     (z == 3) ? Wv : (z == 4) ? W0 : (z == 5) ? W1 : W2;
    const size_t off = (z == 0) ? 0 : (size_t)WSZ_E + (size_t)(z - 1) * WSZ;
    __nv_bfloat16* Th = ThB + off;
    __nv_bfloat16* Tl = TlB + off;

    __shared__ float t[32][33];
    const int tx = threadIdx.x, ty = threadIdx.y;
    const int n = blockIdx.x * 32 + tx;
#pragma unroll
    for (int i = 0; i < 4; i++) {
        const int k = blockIdx.y * 32 + ty + i * 8;
        t[ty + i * 8][tx] = W[(size_t)k * DMODEL + n];
    }
    __syncthreads();
    const int k2 = blockIdx.y * 32 + tx;
#pragma unroll
    for (int i = 0; i < 4; i++) {
        const int n2 = blockIdx.x * 32 + ty + i * 8;
        const float v = t[tx][ty + i * 8];
        const __nv_bfloat16 h = __float2bfloat16(v);
        const __nv_bfloat16 l = __float2bfloat16(v - __bfloat162float(h));
        Th[(size_t)n2 * K + k2] = h;
        Tl[(size_t)n2 * K + k2] = l;
    }
}

__global__ void __launch_bounds__(256)
xsplit(const float* __restrict__ X, __nv_bfloat16* __restrict__ H,
       __nv_bfloat16* __restrict__ L)
{
    const int i = blockIdx.x * 256 + threadIdx.x;
    const float2 v = ((const float2*)X)[i];
    const __nv_bfloat16 hx = __float2bfloat16(v.x);
    const __nv_bfloat16 hy = __float2bfloat16(v.y);
    __nv_bfloat162 hp, lp;
    hp.x = hx; hp.y = hy;
    lp.x = __float2bfloat16(v.x - __bfloat162float(hx));
    lp.y = __float2bfloat16(v.y - __bfloat162float(hy));
    ((__nv_bfloat162*)H)[i] = hp;
    ((__nv_bfloat162*)L)[i] = lp;
}

// ============================================================================
// GEMM: CTA tile 128x256, BK=32, 256 threads = 8 warps (2m x 4n),
// warp tile 64x64 (4 m-frags x 8 n-frags).
// MMA schedule is PASS-MAJOR: all frags loaded first, then 3 sweeps over all
// 32 accumulators (ah*bh, ah*bl, al*bh) -> same-acc reuse distance 32 MMAs
// (was 1), hiding HMMA latency.
// Double-buffered cp.async smem @ 80B row stride (conflict-free ldmatrix).
// ============================================================================
#define GA_TILE 10240
#define GB_TILE 20480
#define GBUF    (2*GA_TILE + 2*GB_TILE)   // 61440
#define GEMM_SMEM (2*GBUF)                // 122880

#define GEMM_MAINLOOP(K_)                                                       \
    float acc[4][8][4];                                                         \
    _Pragma("unroll")                                                           \
    for (int mf = 0; mf < 4; mf++)                                              \
        _Pragma("unroll")                                                       \
        for (int nf = 0; nf < 8; nf++)                                          \
            _Pragma("unroll")                                                   \
            for (int j = 0; j < 4; j++) acc[mf][nf][j] = 0.f;                   \
    const int NIT = (K_) >> 5;                                                  \
    auto issue = [&](int it) {                                                  \
        const int k0 = it << 5;                                                 \
        const uint32_t db = sb + (uint32_t)(it & 1) * GBUF;                     \
        _Pragma("unroll")                                                       \
        for (int t = 0; t < 2; t++) {                                           \
            _Pragma("unroll")                                                   \
            for (int s = 0; s < 2; s++) {                                       \
                const int id = tid + s * 256;                                   \
                const int row = id >> 2, c = id & 3;                            \
                const __nv_bfloat16* g = srcs[t] + (size_t)row * (K_) + k0 + c * 8; \
                CP_ASYNC16(db + (uint32_t)t * GA_TILE                           \
                           + (uint32_t)(row * 80 + c * 16), g);                 \
            }                                                                   \
        }                                                                       \
        _Pragma("unroll")                                                       \
        for (int t = 0; t < 2; t++) {                                           \
            _Pragma("unroll")                                                   \
            for (int s = 0; s < 4; s++) {                                       \
                const int id = tid + s * 256;                                   \
                const int row = id >> 2, c = id & 3;                            \
                const __nv_bfloat16* g = srcs[2 + t] + (size_t)row * (K_) + k0 + c * 8; \
                CP_ASYNC16(db + 2u * GA_TILE + (uint32_t)t * GB_TILE            \
                           + (uint32_t)(row * 80 + c * 16), g);                 \
            }                                                                   \
        }                                                                       \
        CP_COMMIT();                                                            \
    };                                                                          \
    issue(0);                                                                   \
    const int a_r  = lane & 15;                                                 \
    const int a_kh = lane >> 4;                                                 \
    const int b_nl = (lane & 7) + ((lane >> 4) << 3);                           \
    const int b_kh = (lane >> 3) & 1;                                           \
    for (int it = 0; it < NIT; it++) {                                          \
        if (it + 1 < NIT) { issue(it + 1); CP_WAIT1(); }                        \
        else              { CP_WAIT0(); }                                       \
        __syncthreads();                                                        \
        const uint32_t db = sb + (uint32_t)(it & 1) * GBUF;                     \
        _Pragma("unroll")                                                       \
        for (int ks = 0; ks < 2; ks++) {                                        \
            uint32_t ah[4][4], al[4][4], bh[8][2], bl[8][2];                    \
            _Pragma("unroll")                                                   \
            for (int mf = 0; mf < 4; mf++) {                                    \
                const uint32_t aoff = (uint32_t)((wm * 64 + mf * 16 + a_r) * 80 \
                                               + (ks * 16 + a_kh * 8) * 2);     \
                LDSM4(ah[mf][0], ah[mf][1], ah[mf][2], ah[mf][3], db + aoff);   \
                LDSM4(al[mf][0], al[mf][1], al[mf][2], al[mf][3],               \
                      db + GA_TILE + aoff);                                     \
            }                                                                   \
            _Pragma("unroll")                                                   \
            for (int nf2 = 0; nf2 < 4; nf2++) {                                 \
                const uint32_t boff = (uint32_t)((wn * 64 + nf2 * 16 + b_nl) * 80 \
                                               + (ks * 16 + b_kh * 8) * 2);     \
                LDSM4(bh[2*nf2][0], bh[2*nf2][1], bh[2*nf2+1][0], bh[2*nf2+1][1], \
                      db + 2u * GA_TILE + boff);                                \
                LDSM4(bl[2*nf2][0], bl[2*nf2][1], bl[2*nf2+1][0], bl[2*nf2+1][1], \
                      db + 2u * GA_TILE + GB_TILE + boff);                      \
            }                                                                   \
            _Pragma("unroll")                                                   \
            for (int mf = 0; mf < 4; mf++)                                      \
                _Pragma("unroll")                                               \
                for (int nf = 0; nf < 8; nf++)                                  \
                    MMA16816(acc[mf][nf], ah[mf], bh[nf]);                      \
            _Pragma("unroll")                                                   \
            for (int mf = 0; mf < 4; mf++)                                      \
                _Pragma("unroll")                                               \
                for (int nf = 0; nf < 8; nf++)                                  \
                    MMA16816(acc[mf][nf], ah[mf], bl[nf]);                      \
            _Pragma("unroll")                                                   \
            for (int mf = 0; mf < 4; mf++)                                      \
                _Pragma("unroll")                                               \
                for (int nf = 0; nf < 8; nf++)                                  \
                    MMA16816(acc[mf][nf], al[mf], bh[nf]);                      \
        }                                                                       \
        __syncthreads();                                                        \
    }

// ---- generic GEMM: optional fp32 out, bf16 hi/lo out, bias/relu/residual ----
__global__ void __launch_bounds__(256)
gemm_mma(const __nv_bfloat16* __restrict__ Ah, const __nv_bfloat16* __restrict__ Al,
         const __nv_bfloat16* __restrict__ Bh, const __nv_bfloat16* __restrict__ Bl,
         const float* __restrict__ bias, const float* __restrict__ res,
         float* __restrict__ Cf, __nv_bfloat16* __restrict__ Ch,
         __nv_bfloat16* __restrict__ Cl, int K, int relu)
{
    extern __shared__ char smem[];
    const uint32_t sb = smem_u32(smem);
    const int tid  = threadIdx.x;
    const int wid  = tid >> 5;
    const int lane = tid & 31;
    const int wm = wid >> 2;          // 0..1
    const int wn = wid & 3;           // 0..3
    const int m0 = blockIdx.y * 128;
    const int n0 = blockIdx.x * 256;

    const __nv_bfloat16* srcs[4] = {
        Ah + (size_t)m0 * K, Al + (size_t)m0 * K,
        Bh + (size_t)n0 * K, Bl + (size_t)n0 * K };

    GEMM_MAINLOOP(K)

    const int g  = lane >> 2;
    const int i2 = (lane & 3) << 1;
#pragma unroll
    for (int mf = 0; mf < 4; mf++) {
        const int rowa = m0 + wm * 64 + mf * 16 + g;
        const int rowb = rowa + 8;
#pragma unroll
        for (int nf = 0; nf < 8; nf++) {
            const int col = n0 + wn * 64 + nf * 8 + i2;
            const float2 b2 = *(const float2*)&bias[col];
            float v0 = acc[mf][nf][0] + b2.x;
            float v1 = acc[mf][nf][1] + b2.y;
            float v2 = acc[mf][nf][2] + b2.x;
            float v3 = acc[mf][nf][3] + b2.y;
            if (relu) {
                v0 = fmaxf(v0, 0.f); v1 = fmaxf(v1, 0.f);
                v2 = fmaxf(v2, 0.f); v3 = fmaxf(v3, 0.f);
            }
            if (res) {
                const float2 ra = *(const float2*)&res[(size_t)rowa * DMODEL + col];
                const float2 rb = *(const float2*)&res[(size_t)rowb * DMODEL + col];
                v0 += ra.x; v1 += ra.y; v2 += rb.x; v3 += rb.y;
            }
            if (Cf) {
                *(float2*)&Cf[(size_t)rowa * DMODEL + col] = make_float2(v0, v1);
                *(float2*)&Cf[(size_t)rowb * DMODEL + col] = make_float2(v2, v3);
            }
            if (Ch) {
                __nv_bfloat162 hp, lp;
                hp.x = __float2bfloat16(v0); hp.y = __float2bfloat16(v1);
                lp.x = __float2bfloat16(v0 - __bfloat162float(hp.x));
                lp.y = __float2bfloat16(v1 - __bfloat162float(hp.y));
                *(__nv_bfloat162*)&Ch[(size_t)rowa * DMODEL + col] = hp;
                *(__nv_bfloat162*)&Cl[(size_t)rowa * DMODEL + col] = lp;
                hp.x = __float2bfloat16(v2); hp.y = __float2bfloat16(v3);
                lp.x = __float2bfloat16(v2 - __bfloat162float(hp.x));
                lp.y = __float2bfloat16(v3 - __bfloat162float(hp.y));
                *(__nv_bfloat162*)&Ch[(size_t)rowb * DMODEL + col] = hp;
                *(__nv_bfloat162*)&Cl[(size_t)rowb * DMODEL + col] = lp;
            }
        }
    }
}

// ---- fused QKV GEMM: N=3072 (Wq|Wk|Wv contiguous), epilogue routes output ----
__global__ void __launch_bounds__(256)
gemm_qkv(const __nv_bfloat16* __restrict__ Ah, const __nv_bfloat16* __restrict__ Al,
         const __nv_bfloat16* __restrict__ Bh, const __nv_bfloat16* __restrict__ Bl,
         const float* __restrict__ bq, const float* __restrict__ bk,
         const float* __restrict__ bv,
         __nv_bfloat16* __restrict__ qh, __nv_bfloat16* __restrict__ ql,
         __nv_bfloat16* __restrict__ kh, __nv_bfloat16* __restrict__ kl,
         __nv_bfloat16* __restrict__ vh, __nv_bfloat16* __restrict__ vl)
{
    extern __shared__ char smem[];
    const uint32_t sb = smem_u32(smem);
    const int tid  = threadIdx.x;
    const int wid  = tid >> 5;
    const int lane = tid & 31;
    const int wm = wid >> 2;
    const int wn = wid & 3;
    const int m0 = blockIdx.y * 128;
    const int n0 = blockIdx.x * 256;      // global n in [0, 3072)
    const int K = DMODEL;

    const __nv_bfloat16* srcs[4] = {
        Ah + (size_t)m0 * K, Al + (size_t)m0 * K,
        Bh + (size_t)n0 * K, Bl + (size_t)n0 * K };

    GEMM_MAINLOOP(K)

    const int selq = n0 >> 10;
    const int nc0  = n0 & 1023;
    const float* bias = (selq == 0) ? bq : (selq == 1) ? bk : bv;
    __nv_bfloat16* Oh = (selq == 0) ? qh : (selq == 1) ? kh : vh;
    __nv_bfloat16* Ol = (selq == 0) ? ql : (selq == 1) ? kl : vl;

    const int g  = lane >> 2;
    const int i2 = (lane & 3) << 1;
#pragma unroll
    for (int mf = 0; mf < 4; mf++) {
        const int rowa = m0 + wm * 64 + mf * 16 + g;
        const int rowb = rowa + 8;
#pragma unroll
        for (int nf = 0; nf < 8; nf++) {
            const int col = nc0 + wn * 64 + nf * 8 + i2;
            const float2 b2 = *(const float2*)&bias[col];
            const float v0 = acc[mf][nf][0] + b2.x;
            const float v1 = acc[mf][nf][1] + b2.y;
            const float v2 = acc[mf][nf][2] + b2.x;
            const float v3 = acc[mf][nf][3] + b2.y;
            __nv_bfloat162 hp, lp;
            hp.x = __float2bfloat16(v0); hp.y = __float2bfloat16(v1);
            lp.x = __float2bfloat16(v0 - __bfloat162float(hp.x));
            lp.y = __float2bfloat16(v1 - __bfloat162float(hp.y));
            *(__nv_bfloat162*)&Oh[(size_t)rowa * DMODEL + col] = hp;
            *(__nv_bfloat162*)&Ol[(size_t)rowa * DMODEL + col] = lp;
            hp.x = __float2bfloat16(v2); hp.y = __float2bfloat16(v3);
            lp.x = __float2bfloat16(v2 - __bfloat162float(hp.x));
            lp.y = __float2bfloat16(v3 - __bfloat162float(hp.y));
            *(__nv_bfloat162*)&Oh[(size_t)rowb * DMODEL + col] = hp;
            *(__nv_bfloat162*)&Ol[(size_t)rowb * DMODEL + col] = lp;
        }
    }
}

// ============================================================================
// Tensor-core flash attention (unchanged from R9 WIN).
// ============================================================================
#define AT_STR    144
#define AT_QTILE  (128*AT_STR)
#define AT_KVT    (64*AT_STR)
#define AT_BUF    (4*AT_KVT)
#define AT_Q      (2*AT_QTILE)
#define AT_SMEM   (AT_Q + 2*AT_BUF)     // 110592

__global__ void __launch_bounds__(256, 1)
attn_mma(const __nv_bfloat16* __restrict__ Qh, const __nv_bfloat16* __restrict__ Ql,
         const __nv_bfloat16* __restrict__ Kh, const __nv_bfloat16* __restrict__ Kl,
         const __nv_bfloat16* __restrict__ Vh, const __nv_bfloat16* __restrict__ Vl,
         __nv_bfloat16* __restrict__ Ch, __nv_bfloat16* __restrict__ Cl)
{
    extern __shared__ char smem[];
    const uint32_t sb = smem_u32(smem);
    const int tid  = threadIdx.x;
    const int wid  = tid >> 5;
    const int lane = tid & 31;
    const int q0   = blockIdx.x * 128;
    const int bh   = blockIdx.y;
    const int b    = bh >> 4;
    const int h    = bh & (NHEAD - 1);
    const size_t base = (size_t)b * SEQ * DMODEL + (size_t)h * 64;
    const float scale = 0.125f;

    const __nv_bfloat16* kvs[4] = { Kh + base, Kl + base, Vh + base, Vl + base };

    auto issue = [&](int it) {
        const int kv0 = it << 6;
        const uint32_t db = sb + AT_Q + (uint32_t)(it & 1) * AT_BUF;
#pragma unroll
        for (int t = 0; t < 4; t++) {
#pragma unroll
            for (int s = 0; s < 2; s++) {
                const int id = tid + s * 256;
                const int row = id >> 3, c16 = id & 7;
                const __nv_bfloat16* g = kvs[t] + (size_t)(kv0 + row) * DMODEL + c16 * 8;
                const uint32_t d = db + (uint32_t)t * AT_KVT + (uint32_t)(row * AT_STR + c16 * 16);
                CP_ASYNC16(d, g);
            }
        }
        CP_COMMIT();
    };

    issue(0);

#pragma unroll
    for (int s = 0; s < 4; s++) {
        const int id = tid + s * 256;
        const int row = id >> 3, c16 = id & 7;
        const size_t g = base + (size_t)(q0 + row) * DMODEL + c16 * 8;
        const uint32_t d = (uint32_t)(row * AT_STR + c16 * 16);
        *(uint4*)(smem + d)            = *(const uint4*)(Qh + g);
        *(uint4*)(smem + AT_QTILE + d) = *(const uint4*)(Ql + g);
    }
    __syncthreads();

    const int tq  = lane & 7;
    const int sel = lane >> 3;
    const int wq0 = wid * 16;
    uint32_t qfh[4][4], qfl[4][4];
    {
        const int arow = wq0 + tq + (sel & 1) * 8;
#pragma unroll
        for (int ks = 0; ks < 4; ks++) {
            const uint32_t a = sb + (uint32_t)(arow * AT_STR + (ks * 16 + (sel >> 1) * 8) * 2);
            LDSM4(qfh[ks][0], qfh[ks][1], qfh[ks][2], qfh[ks][3], a);
            LDSM4(qfl[ks][0], qfl[ks][1], qfl[ks][2], qfl[ks][3], a + AT_QTILE);
        }
    }

    float oacc[8][4];
#pragma unroll
    for (int nf = 0; nf < 8; nf++)
#pragma unroll
        for (int j = 0; j < 4; j++) oacc[nf][j] = 0.f;
    float m0 = -1e30f, m1 = -1e30f, l0 = 0.f, l1 = 0.f;

    const int NIT = SEQ / 64;
    for (int it = 0; it < NIT; it++) {
        if (it + 1 < NIT) { issue(it + 1); CP_WAIT1(); }
        else              { CP_WAIT0(); }
        __syncthreads();
        const uint32_t db = sb + AT_Q + (uint32_t)(it & 1) * AT_BUF;

        float sacc[8][4];
#pragma unroll
        for (int nf = 0; nf < 8; nf++)
#pragma unroll
            for (int j = 0; j < 4; j++) sacc[nf][j] = 0.f;

#pragma unroll
        for (int ks = 0; ks < 4; ks++) {
            uint32_t bf[8][2];
#pragma unroll
            for (int p = 0; p < 4; p++) {
                const uint32_t a = db + (uint32_t)(((p * 16) + tq + (sel >> 1) * 8) * AT_STR
                                                 + (ks * 16 + (sel & 1) * 8) * 2);
                LDSM4(bf[2*p][0], bf[2*p][1], bf[2*p+1][0], bf[2*p+1][1], a);
            }
#pragma unroll
            for (int nf = 0; nf < 8; nf++) MMA16816(sacc[nf], qfh[ks], bf[nf]);
#pragma unroll
            for (int nf = 0; nf < 8; nf++) MMA16816(sacc[nf], qfl[ks], bf[nf]);
        }
#pragma unroll
        for (int ks = 0; ks < 4; ks++) {
            uint32_t bf[8][2];
#pragma unroll
            for (int p = 0; p < 4; p++) {
                const uint32_t a = db + AT_KVT + (uint32_t)(((p * 16) + tq + (sel >> 1) * 8) * AT_STR
                                                           + (ks * 16 + (sel & 1) * 8) * 2);
                LDSM4(bf[2*p][0], bf[2*p][1], bf[2*p+1][0], bf[2*p+1][1], a);
            }
#pragma unroll
            for (int nf = 0; nf < 8; nf++) MMA16816(sacc[nf], qfh[ks], bf[nf]);
        }

#pragma unroll
        for (int nf = 0; nf < 8; nf++)
#pragma unroll
            for (int j = 0; j < 4; j++) sacc[nf][j] *= scale;

        float mx0 = -1e30f, mx1 = -1e30f;
#pragma unroll
        for (int nf = 0; nf < 8; nf++) {
            mx0 = fmaxf(mx0, fmaxf(sacc[nf][0], sacc[nf][1]));
            mx1 = fmaxf(mx1, fmaxf(sacc[nf][2], sacc[nf][3]));
        }
        mx0 = fmaxf(mx0, __shfl_xor_sync(0xffffffffu, mx0, 1));
        mx0 = fmaxf(mx0, __shfl_xor_sync(0xffffffffu, mx0, 2));
        mx1 = fmaxf(mx1, __shfl_xor_sync(0xffffffffu, mx1, 1));
        mx1 = fmaxf(mx1, __shfl_xor_sync(0xffffffffu, mx1, 2));

        const float mn0 = fmaxf(m0, mx0);
        const float mn1 = fmaxf(m1, mx1);
        const float al0 = __expf(m0 - mn0);
        const float al1 = __expf(m1 - mn1);
        m0 = mn0; m1 = mn1;

        uint32_t ph[4][4], pl[4][4];
        float sum0 = 0.f, sum1 = 0.f;
#pragma unroll
        for (int nf = 0; nf < 8; nf++) {
            const float p0 = __expf(sacc[nf][0] - m0);
            const float p1 = __expf(sacc[nf][1] - m0);
            const float p2 = __expf(sacc[nf][2] - m1);
            const float p3 = __expf(sacc[nf][3] - m1);
            sum0 += p0 + p1;
            sum1 += p2 + p3;
            const int kf = nf >> 1, hf = (nf & 1) * 2;
            const uint32_t h01 = packbf2(p0, p1);
            const uint32_t h23 = packbf2(p2, p3);
            ph[kf][hf]     = h01;
            ph[kf][hf + 1] = h23;
            const __nv_bfloat162 hb01 = *(const __nv_bfloat162*)&h01;
            const __nv_bfloat162 hb23 = *(const __nv_bfloat162*)&h23;
            pl[kf][hf]     = packbf2(p0 - __bfloat162float(hb01.x), p1 - __bfloat162float(hb01.y));
            pl[kf][hf + 1] = packbf2(p2 - __bfloat162float(hb23.x), p3 - __bfloat162float(hb23.y));
        }
        sum0 += __shfl_xor_sync(0xffffffffu, sum0, 1);
        sum0 += __shfl_xor_sync(0xffffffffu, sum0, 2);
        sum1 += __shfl_xor_sync(0xffffffffu, sum1, 1);
        sum1 += __shfl_xor_sync(0xffffffffu, sum1, 2);
        l0 = l0 * al0 + sum0;
        l1 = l1 * al1 + sum1;
#pragma unroll
        for (int nf = 0; nf < 8; nf++) {
            oacc[nf][0] *= al0; oacc[nf][1] *= al0;
            oacc[nf][2] *= al1; oacc[nf][3] *= al1;
        }

#pragma unroll
        for (int kst = 0; kst < 4; kst++) {
            uint32_t vf[8][2];
#pragma unroll
            for (int p = 0; p < 4; p++) {
                const uint32_t a = db + 2u * AT_KVT
                    + (uint32_t)((kst * 16 + tq + (sel & 1) * 8) * AT_STR
                               + (p * 16 + (sel >> 1) * 8) * 2);
                LDSM4T(vf[2*p][0], vf[2*p][1], vf[2*p+1][0], vf[2*p+1][1], a);
            }
#pragma unroll
            for (int nf = 0; nf < 8; nf++) MMA16816(oacc[nf], ph[kst], vf[nf]);
#pragma unroll
            for (int nf = 0; nf < 8; nf++) MMA16816(oacc[nf], pl[kst], vf[nf]);
        }
#pragma unroll
        for (int kst = 0; kst < 4; kst++) {
            uint32_t vf[8][2];
#pragma unroll
            for (int p = 0; p < 4; p++) {
                const uint32_t a = db + 3u * AT_KVT
                    + (uint32_t)((kst * 16 + tq + (sel & 1) * 8) * AT_STR
                               + (p * 16 + (sel >> 1) * 8) * 2);
                LDSM4T(vf[2*p][0], vf[2*p][1], vf[2*p+1][0], vf[2*p+1][1], a);
            }
#pragma unroll
            for (int nf = 0; nf < 8; nf++) MMA16816(oacc[nf], ph[kst], vf[nf]);
        }
        __syncthreads();
    }

    const float inv0 = 1.f / l0;
    const float inv1 = 1.f / l1;
    const int g  = lane >> 2;
    const int i2 = (lane & 3) << 1;
    const int row0 = q0 + wq0 + g;
    const int row1 = row0 + 8;
#pragma unroll
    for (int nf = 0; nf < 8; nf++) {
        const int coff = nf * 8 + i2;
        const float v0 = oacc[nf][0] * inv0;
        const float v1 = oacc[nf][1] * inv0;
        const float v2 = oacc[nf][2] * inv1;
        const float v3 = oacc[nf][3] * inv1;
        __nv_bfloat162 hp, lp;
        hp.x = __float2bfloat16(v0); hp.y = __float2bfloat16(v1);
        lp.x = __float2bfloat16(v0 - __bfloat162float(hp.x));
        lp.y = __float2bfloat16(v1 - __bfloat162float(hp.y));
        *(__nv_bfloat162*)&Ch[base + (size_t)row0 * DMODEL + coff] = hp;
        *(__nv_bfloat162*)&Cl[base + (size_t)row0 * DMODEL + coff] = lp;
        hp.x = __float2bfloat16(v2); hp.y = __float2bfloat16(v3);
        lp.x = __float2bfloat16(v2 - __bfloat162float(hp.x));
        lp.y = __float2bfloat16(v3 - __bfloat162float(hp.y));
        *(__nv_bfloat162*)&Ch[base + (size_t)row1 * DMODEL + coff] = hp;
        *(__nv_bfloat162*)&Cl[base + (size_t)row1 * DMODEL + coff] = lp;
    }
}

// ============================================================================
// kernel_launch
// ============================================================================
extern "C" void kernel_launch(void* const* d_in, const int* in_sizes, int n_in,
                              void* d_out, int out_size)
{
    (void)in_sizes; (void)n_in; (void)out_size;

    const float* x  = (const float*)d_in[0];
    const float* We = (const float*)d_in[1];
    const float* be = (const float*)d_in[2];
    const float* Wq = (const float*)d_in[3];
    const float* bq = (const float*)d_in[4];
    const float* Wk = (const float*)d_in[5];
    const float* bk = (const float*)d_in[6];
    const float* Wv = (const float*)d_in[7];
    const float* bv = (const float*)d_in[8];
    const float* W0 = (const float*)d_in[9];
    const float* b0 = (const float*)d_in[10];
    const float* W1 = (const float*)d_in[11];
    const float* b1 = (const float*)d_in[12];
    const float* W2 = (const float*)d_in[13];
    const float* b2 = (const float*)d_in[14];
    float* out = (float*)d_out;

    float *e, *mha;
    __nv_bfloat16 *xh, *xl, *eh, *el, *qh, *ql, *kh, *kl, *vh, *vl;
    __nv_bfloat16 *ch, *cl, *mh, *ml, *hh, *hl, *Wth, *Wtl;
    cudaGetSymbolAddress((void**)&e,   g_e);
    cudaGetSymbolAddress((void**)&mha, g_mha);
    cudaGetSymbolAddress((void**)&xh,  g_xh);
    cudaGetSymbolAddress((void**)&xl,  g_xl);
    cudaGetSymbolAddress((void**)&eh,  g_eh);
    cudaGetSymbolAddress((void**)&el,  g_el);
    cudaGetSymbolAddress((void**)&qh,  g_qh);
    cudaGetSymbolAddress((void**)&ql,  g_ql);
    cudaGetSymbolAddress((void**)&kh,  g_kh);
    cudaGetSymbolAddress((void**)&kl,  g_kl);
    cudaGetSymbolAddress((void**)&vh,  g_vh);
    cudaGetSymbolAddress((void**)&vl,  g_vl);
    cudaGetSymbolAddress((void**)&ch,  g_ch);
    cudaGetSymbolAddress((void**)&cl,  g_cl);
    cudaGetSymbolAddress((void**)&mh,  g_mh);
    cudaGetSymbolAddress((void**)&ml,  g_ml);
    cudaGetSymbolAddress((void**)&hh,  g_hh);
    cudaGetSymbolAddress((void**)&hl,  g_hl);
    cudaGetSymbolAddress((void**)&Wth, g_Wth);
    cudaGetSymbolAddress((void**)&Wtl, g_Wtl);

    cudaFuncSetAttribute(gemm_mma, cudaFuncAttributeMaxDynamicSharedMemorySize, GEMM_SMEM);
    cudaFuncSetAttribute(gemm_qkv, cudaFuncAttributeMaxDynamicSharedMemorySize, GEMM_SMEM);
    cudaFuncSetAttribute(attn_mma, cudaFuncAttributeMaxDynamicSharedMemorySize, AT_SMEM);

    // all weight transposes+splits in one launch; x split
    wsplit_all<<<dim3(32, 32, 7), dim3(32, 8)>>>(We, Wq, Wk, Wv, W0, W1, W2, Wth, Wtl);
    xsplit<<<MROWS * DIN / 512, 256>>>(x, xh, xl);

    __nv_bfloat16* Wqh = Wth + WSZ_E;  __nv_bfloat16* Wql = Wtl + WSZ_E;
    __nv_bfloat16* W0h = Wqh + 3*WSZ;  __nv_bfloat16* W0l = Wql + 3*WSZ;
    __nv_bfloat16* W1h = W0h + WSZ;    __nv_bfloat16* W1l = W0l + WSZ;
    __nv_bfloat16* W2h = W1h + WSZ;    __nv_bfloat16* W2l = W1l + WSZ;

    const dim3 gg(4, 32);   // (N/256, M/128)
    // e = x @ We + be  (fp32 + hi/lo)
    gemm_mma<<<gg, 256, GEMM_SMEM>>>(xh, xl, Wth, Wtl, be, nullptr, e, eh, el, DIN, 0);
    // q,k,v fused (bf16 hi/lo)
    gemm_qkv<<<dim3(12, 32), 256, GEMM_SMEM>>>(eh, el, Wqh, Wql, bq, bk, bv,
                                               qh, ql, kh, kl, vh, vl);
    // attention -> ctx (bf16 hi/lo)
    attn_mma<<<dim3(SEQ / 128, 32), 256, AT_SMEM>>>(qh, ql, kh, kl, vh, vl, ch, cl);
    // mha = e + ctx @ W0 + b0  (fp32 + hi/lo)
    gemm_mma<<<gg, 256, GEMM_SMEM>>>(ch, cl, W0h, W0l, b0, e, mha, mh, ml, DMODEL, 0);
    // h1 = relu(mha @ W1 + b1)  (hi/lo only)
    gemm_mma<<<gg, 256, GEMM_SMEM>>>(mh, ml, W1h, W1l, b1, nullptr, nullptr, hh, hl, DMODEL, 1);
    // out = mha + h1 @ W2 + b2  (fp32)
    gemm_mma<<<gg, 256, GEMM_SMEM>>>(hh, hl, W2h, W2l, b2, mha, out, nullptr, nullptr, DMODEL, 0);
}

// round 14
// speedup vs baseline: 1.4061x; 1.4061x over previous
#include <cuda_runtime.h>
#include <cuda_fp16.h>
#include <cstdint>

#define MROWS  4096
#define DMODEL 1024
#define DIN    512
#define NHEAD  16
#define SEQ    2048

// ---------------- scratch (allocation-free) ----------------
__device__ __align__(128) float g_e  [MROWS*DMODEL];
__device__ __align__(128) float g_mha[MROWS*DMODEL];
__device__ __align__(128) __half g_xh[MROWS*DIN],    g_xl[MROWS*DIN];
__device__ __align__(128) __half g_eh[MROWS*DMODEL], g_el[MROWS*DMODEL];
__device__ __align__(128) __half g_qh[MROWS*DMODEL], g_ql[MROWS*DMODEL];
__device__ __align__(128) __half g_kh[MROWS*DMODEL];
__device__ __align__(128) __half g_vh[MROWS*DMODEL];
__device__ __align__(128) __half g_ch[MROWS*DMODEL], g_cl[MROWS*DMODEL];
__device__ __align__(128) __half g_mh[MROWS*DMODEL], g_ml[MROWS*DMODEL];
__device__ __align__(128) __half g_hh[MROWS*DMODEL], g_hl[MROWS*DMODEL];
#define WSZ_E (DMODEL*DIN)
#define WSZ   (DMODEL*DMODEL)
__device__ __align__(128) __half g_Wh[WSZ_E + 6*WSZ];

// ---------------- helpers ----------------
__device__ __forceinline__ uint32_t smem_u32(const void* p) {
    uint32_t a;
    asm("{ .reg .u64 t; cvta.to.shared.u64 t, %1; cvt.u32.u64 %0, t; }" : "=r"(a) : "l"(p));
    return a;
}

#define CP_ASYNC16(dst, src) \
    asm volatile("cp.async.cg.shared.global [%0], [%1], 16;" :: "r"(dst), "l"(src) : "memory")
#define CP_COMMIT()  asm volatile("cp.async.commit_group;" ::: "memory")
#define CP_WAIT1()   asm volatile("cp.async.wait_group 1;" ::: "memory")
#define CP_WAIT0()   asm volatile("cp.async.wait_group 0;" ::: "memory")

#define LDSM4(r0, r1, r2, r3, a) \
    asm volatile("ldmatrix.sync.aligned.m8n8.x4.shared.b16 {%0,%1,%2,%3}, [%4];" \
                 : "=r"(r0), "=r"(r1), "=r"(r2), "=r"(r3) : "r"(a))
#define LDSM4T(r0, r1, r2, r3, a) \
    asm volatile("ldmatrix.sync.aligned.m8n8.x4.trans.shared.b16 {%0,%1,%2,%3}, [%4];" \
                 : "=r"(r0), "=r"(r1), "=r"(r2), "=r"(r3) : "r"(a))

#define MMA16816(d, a, b) \
    asm volatile("mma.sync.aligned.m16n8k16.row.col.f32.f16.f16.f32 " \
                 "{%0,%1,%2,%3}, {%4,%5,%6,%7}, {%8,%9}, {%0,%1,%2,%3};" \
                 : "+f"((d)[0]), "+f"((d)[1]), "+f"((d)[2]), "+f"((d)[3]) \
                 : "r"((a)[0]), "r"((a)[1]), "r"((a)[2]), "r"((a)[3]), \
                   "r"((b)[0]), "r"((b)[1]))

__device__ __forceinline__ uint32_t packh2(float a, float b) {
    __half2 t;
    t.x = __float2half_rn(a);
    t.y = __float2half_rn(b);
    return *(uint32_t*)&t;
}

// ============================================================================
// Fused weight transpose + fp16 cast for all 7 weights (grid.z selects).
// W[K][N] fp32 -> Th[N][K] fp16 (no lo term needed: 2-pass split drops it).
// ============================================================================
__global__ void __launch_bounds__(256)
wsplit_all(const float* __restrict__ We, const float* __restrict__ Wq,
           const float* __restrict__ Wk, const float* __restrict__ Wv,
           const float* __restrict__ W0, const float* __restrict__ W1,
           const float* __restrict__ W2, __half* __restrict__ ThB)
{
    const int z = blockIdx.z;
    const int K = (z == 0) ? DIN : DMODEL;
    if ((int)blockIdx.y * 32 >= K) return;
    const float* W = (z == 0) ? We : (z == 1) ? Wq : (z == 2) ? Wk :
                     (z == 3) ? Wv : (z == 4) ? W0 : (z == 5) ? W1 : W2;
    const size_t off = (z == 0) ? 0 : (size_t)WSZ_E + (size_t)(z - 1) * WSZ;
    __half* Th = ThB + off;

    __shared__ float t[32][33];
    const int tx = threadIdx.x, ty = threadIdx.y;
    const int n = blockIdx.x * 32 + tx;
#pragma unroll
    for (int i = 0; i < 4; i++) {
        const int k = blockIdx.y * 32 + ty + i * 8;
        t[ty + i * 8][tx] = W[(size_t)k * DMODEL + n];
    }
    __syncthreads();
    const int k2 = blockIdx.y * 32 + tx;
#pragma unroll
    for (int i = 0; i < 4; i++) {
        const int n2 = blockIdx.x * 32 + ty + i * 8;
        Th[(size_t)n2 * K + k2] = __float2half_rn(t[tx][ty + i * 8]);
    }
}

__global__ void __launch_bounds__(256)
xsplit(const float* __restrict__ X, __half* __restrict__ H, __half* __restrict__ L)
{
    const int i = blockIdx.x * 256 + threadIdx.x;
    const float2 v = ((const float2*)X)[i];
    const __half hx = __float2half_rn(v.x);
    const __half hy = __float2half_rn(v.y);
    __half2 hp, lp;
    hp.x = hx; hp.y = hy;
    lp.x = __float2half_rn(v.x - __half2float(hx));
    lp.y = __float2half_rn(v.y - __half2float(hy));
    ((__half2*)H)[i] = hp;
    ((__half2*)L)[i] = lp;
}

// ============================================================================
// GEMM: CTA tile 128x256, BK=32, 256 threads = 8 warps (2m x 4n),
// warp tile 64x64. fp16 2-pass: C = Ah*Wh + Al*Wh (weight-lo dropped).
// Smem per buffer: Ah,Al 128x80B (10240) + Bh 256x80B (20480) = 40960; x2.
// ============================================================================
#define GA_TILE 10240
#define GB_TILE 20480
#define GBUF    (2*GA_TILE + GB_TILE)     // 40960
#define GEMM_SMEM (2*GBUF)                // 81920

#define GEMM_MAINLOOP(K_)                                                       \
    float acc[4][8][4];                                                         \
    _Pragma("unroll")                                                           \
    for (int mf = 0; mf < 4; mf++)                                              \
        _Pragma("unroll")                                                       \
        for (int nf = 0; nf < 8; nf++)                                          \
            _Pragma("unroll")                                                   \
            for (int j = 0; j < 4; j++) acc[mf][nf][j] = 0.f;                   \
    const int NIT = (K_) >> 5;                                                  \
    auto issue = [&](int it) {                                                  \
        const int k0 = it << 5;                                                 \
        const uint32_t db = sb + (uint32_t)(it & 1) * GBUF;                     \
        _Pragma("unroll")                                                       \
        for (int t = 0; t < 2; t++) {                                           \
            _Pragma("unroll")                                                   \
            for (int s = 0; s < 2; s++) {                                       \
                const int id = tid + s * 256;                                   \
                const int row = id >> 2, c = id & 3;                            \
                const __half* g = srcs[t] + (size_t)row * (K_) + k0 + c * 8;    \
                CP_ASYNC16(db + (uint32_t)t * GA_TILE                           \
                           + (uint32_t)(row * 80 + c * 16), g);                 \
            }                                                                   \
        }                                                                       \
        _Pragma("unroll")                                                       \
        for (int s = 0; s < 4; s++) {                                           \
            const int id = tid + s * 256;                                       \
            const int row = id >> 2, c = id & 3;                                \
            const __half* g = srcs[2] + (size_t)row * (K_) + k0 + c * 8;        \
            CP_ASYNC16(db + 2u * GA_TILE                                        \
                       + (uint32_t)(row * 80 + c * 16), g);                     \
        }                                                                       \
        CP_COMMIT();                                                            \
    };                                                                          \
    issue(0);                                                                   \
    const int a_r  = lane & 15;                                                 \
    const int a_kh = lane >> 4;                                                 \
    const int b_nl = (lane & 7) + ((lane >> 4) << 3);                           \
    const int b_kh = (lane >> 3) & 1;                                           \
    for (int it = 0; it < NIT; it++) {                                          \
        if (it + 1 < NIT) { issue(it + 1); CP_WAIT1(); }                        \
        else              { CP_WAIT0(); }                                       \
        __syncthreads();                                                        \
        const uint32_t db = sb + (uint32_t)(it & 1) * GBUF;                     \
        _Pragma("unroll")                                                       \
        for (int ks = 0; ks < 2; ks++) {                                        \
            uint32_t ah[4][4], al[4][4], bh[8][2];                              \
            _Pragma("unroll")                                                   \
            for (int mf = 0; mf < 4; mf++) {                                    \
                const uint32_t aoff = (uint32_t)((wm * 64 + mf * 16 + a_r) * 80 \
                                               + (ks * 16 + a_kh * 8) * 2);     \
                LDSM4(ah[mf][0], ah[mf][1], ah[mf][2], ah[mf][3], db + aoff);   \
                LDSM4(al[mf][0], al[mf][1], al[mf][2], al[mf][3],               \
                      db + GA_TILE + aoff);                                     \
            }                                                                   \
            _Pragma("unroll")                                                   \
            for (int nf2 = 0; nf2 < 4; nf2++) {                                 \
                const uint32_t boff = (uint32_t)((wn * 64 + nf2 * 16 + b_nl) * 80 \
                                               + (ks * 16 + b_kh * 8) * 2);     \
                LDSM4(bh[2*nf2][0], bh[2*nf2][1], bh[2*nf2+1][0], bh[2*nf2+1][1], \
                      db + 2u * GA_TILE + boff);                                \
            }                                                                   \
            _Pragma("unroll")                                                   \
            for (int mf = 0; mf < 4; mf++)                                      \
                _Pragma("unroll")                                               \
                for (int nf = 0; nf < 8; nf++)                                  \
                    MMA16816(acc[mf][nf], ah[mf], bh[nf]);                      \
            _Pragma("unroll")                                                   \
            for (int mf = 0; mf < 4; mf++)                                      \
                _Pragma("unroll")                                               \
                for (int nf = 0; nf < 8; nf++)                                  \
                    MMA16816(acc[mf][nf], al[mf], bh[nf]);                      \
        }                                                                       \
        __syncthreads();                                                        \
    }

// ---- generic GEMM: optional fp32 out, fp16 hi/lo out, bias/relu/residual ----
__global__ void __launch_bounds__(256)
gemm_mma(const __half* __restrict__ Ah, const __half* __restrict__ Al,
         const __half* __restrict__ Bh,
         const float* __restrict__ bias, const float* __restrict__ res,
         float* __restrict__ Cf, __half* __restrict__ Ch,
         __half* __restrict__ Cl, int K, int relu)
{
    extern __shared__ char smem[];
    const uint32_t sb = smem_u32(smem);
    const int tid  = threadIdx.x;
    const int wid  = tid >> 5;
    const int lane = tid & 31;
    const int wm = wid >> 2;
    const int wn = wid & 3;
    const int m0 = blockIdx.y * 128;
    const int n0 = blockIdx.x * 256;

    const __half* srcs[3] = {
        Ah + (size_t)m0 * K, Al + (size_t)m0 * K, Bh + (size_t)n0 * K };

    GEMM_MAINLOOP(K)

    const int g  = lane >> 2;
    const int i2 = (lane & 3) << 1;
#pragma unroll
    for (int mf = 0; mf < 4; mf++) {
        const int rowa = m0 + wm * 64 + mf * 16 + g;
        const int rowb = rowa + 8;
#pragma unroll
        for (int nf = 0; nf < 8; nf++) {
            const int col = n0 + wn * 64 + nf * 8 + i2;
            const float2 b2 = *(const float2*)&bias[col];
            float v0 = acc[mf][nf][0] + b2.x;
            float v1 = acc[mf][nf][1] + b2.y;
            float v2 = acc[mf][nf][2] + b2.x;
            float v3 = acc[mf][nf][3] + b2.y;
            if (relu) {
                v0 = fmaxf(v0, 0.f); v1 = fmaxf(v1, 0.f);
                v2 = fmaxf(v2, 0.f); v3 = fmaxf(v3, 0.f);
            }
            if (res) {
                const float2 ra = *(const float2*)&res[(size_t)rowa * DMODEL + col];
                const float2 rb = *(const float2*)&res[(size_t)rowb * DMODEL + col];
                v0 += ra.x; v1 += ra.y; v2 += rb.x; v3 += rb.y;
            }
            if (Cf) {
                *(float2*)&Cf[(size_t)rowa * DMODEL + col] = make_float2(v0, v1);
                *(float2*)&Cf[(size_t)rowb * DMODEL + col] = make_float2(v2, v3);
            }
            if (Ch) {
                uint32_t hp = packh2(v0, v1);
                const __half2 h2a = *(const __half2*)&hp;
                uint32_t lp = packh2(v0 - __half2float(h2a.x), v1 - __half2float(h2a.y));
                *(uint32_t*)&Ch[(size_t)rowa * DMODEL + col] = hp;
                *(uint32_t*)&Cl[(size_t)rowa * DMODEL + col] = lp;
                hp = packh2(v2, v3);
                const __half2 h2b = *(const __half2*)&hp;
                lp = packh2(v2 - __half2float(h2b.x), v3 - __half2float(h2b.y));
                *(uint32_t*)&Ch[(size_t)rowb * DMODEL + col] = hp;
                *(uint32_t*)&Cl[(size_t)rowb * DMODEL + col] = lp;
            }
        }
    }
}

// ---- fused QKV GEMM: N=3072 (Wq|Wk|Wv contiguous). q gets hi+lo; k,v hi only.
__global__ void __launch_bounds__(256)
gemm_qkv(const __half* __restrict__ Ah, const __half* __restrict__ Al,
         const __half* __restrict__ Bh,
         const float* __restrict__ bq, const float* __restrict__ bk,
         const float* __restrict__ bv,
         __half* __restrict__ qh, __half* __restrict__ ql,
         __half* __restrict__ kh, __half* __restrict__ vh)
{
    extern __shared__ char smem[];
    const uint32_t sb = smem_u32(smem);
    const int tid  = threadIdx.x;
    const int wid  = tid >> 5;
    const int lane = tid & 31;
    const int wm = wid >> 2;
    const int wn = wid & 3;
    const int m0 = blockIdx.y * 128;
    const int n0 = blockIdx.x * 256;      // global n in [0, 3072)
    const int K = DMODEL;

    const __half* srcs[3] = {
        Ah + (size_t)m0 * K, Al + (size_t)m0 * K, Bh + (size_t)n0 * K };

    GEMM_MAINLOOP(K)

    const int selq = n0 >> 10;
    const int nc0  = n0 & 1023;
    const float* bias = (selq == 0) ? bq : (selq == 1) ? bk : bv;
    __half* Oh = (selq == 0) ? qh : (selq == 1) ? kh : vh;
    __half* Ol = (selq == 0) ? ql : nullptr;

    const int g  = lane >> 2;
    const int i2 = (lane & 3) << 1;
#pragma unroll
    for (int mf = 0; mf < 4; mf++) {
        const int rowa = m0 + wm * 64 + mf * 16 + g;
        const int rowb = rowa + 8;
#pragma unroll
        for (int nf = 0; nf < 8; nf++) {
            const int col = nc0 + wn * 64 + nf * 8 + i2;
            const float2 b2 = *(const float2*)&bias[col];
            const float v0 = acc[mf][nf][0] + b2.x;
            const float v1 = acc[mf][nf][1] + b2.y;
            const float v2 = acc[mf][nf][2] + b2.x;
            const float v3 = acc[mf][nf][3] + b2.y;
            const uint32_t hpa = packh2(v0, v1);
            const uint32_t hpb = packh2(v2, v3);
            *(uint32_t*)&Oh[(size_t)rowa * DMODEL + col] = hpa;
            *(uint32_t*)&Oh[(size_t)rowb * DMODEL + col] = hpb;
            if (Ol) {
                const __half2 h2a = *(const __half2*)&hpa;
                const __half2 h2b = *(const __half2*)&hpb;
                *(uint32_t*)&Ol[(size_t)rowa * DMODEL + col] =
                    packh2(v0 - __half2float(h2a.x), v1 - __half2float(h2a.y));
                *(uint32_t*)&Ol[(size_t)rowb * DMODEL + col] =
                    packh2(v2 - __half2float(h2b.x), v3 - __half2float(h2b.y));
            }
        }
    }
}

// ============================================================================
// Tensor-core flash attention, fp16 2-pass.
// Scores: QhKh + QlKh. PV: PhVh + PlVh. K,V hi only.
// smem: Qh[0,18432) Ql[18432,36864); buf b at 36864 + b*18432: KH, VH (9216 ea)
// ============================================================================
#define AT_STR    144
#define AT_QTILE  (128*AT_STR)          // 18432
#define AT_KVT    (64*AT_STR)           // 9216
#define AT_BUF    (2*AT_KVT)            // 18432
#define AT_Q      (2*AT_QTILE)          // 36864
#define AT_SMEM   (AT_Q + 2*AT_BUF)     // 73728

__global__ void __launch_bounds__(256, 1)
attn_mma(const __half* __restrict__ Qh, const __half* __restrict__ Ql,
         const __half* __restrict__ Kh, const __half* __restrict__ Vh,
         __half* __restrict__ Ch, __half* __restrict__ Cl)
{
    extern __shared__ char smem[];
    const uint32_t sb = smem_u32(smem);
    const int tid  = threadIdx.x;
    const int wid  = tid >> 5;
    const int lane = tid & 31;
    const int q0   = blockIdx.x * 128;
    const int bh   = blockIdx.y;
    const int b    = bh >> 4;
    const int h    = bh & (NHEAD - 1);
    const size_t base = (size_t)b * SEQ * DMODEL + (size_t)h * 64;
    const float scale = 0.125f;

    const __half* kvs[2] = { Kh + base, Vh + base };

    auto issue = [&](int it) {
        const int kv0 = it << 6;
        const uint32_t db = sb + AT_Q + (uint32_t)(it & 1) * AT_BUF;
#pragma unroll
        for (int t = 0; t < 2; t++) {
#pragma unroll
            for (int s = 0; s < 2; s++) {
                const int id = tid + s * 256;
                const int row = id >> 3, c16 = id & 7;
                const __half* g = kvs[t] + (size_t)(kv0 + row) * DMODEL + c16 * 8;
                const uint32_t d = db + (uint32_t)t * AT_KVT + (uint32_t)(row * AT_STR + c16 * 16);
                CP_ASYNC16(d, g);
            }
        }
        CP_COMMIT();
    };

    issue(0);

#pragma unroll
    for (int s = 0; s < 4; s++) {
        const int id = tid + s * 256;
        const int row = id >> 3, c16 = id & 7;
        const size_t g = base + (size_t)(q0 + row) * DMODEL + c16 * 8;
        const uint32_t d = (uint32_t)(row * AT_STR + c16 * 16);
        *(uint4*)(smem + d)            = *(const uint4*)(Qh + g);
        *(uint4*)(smem + AT_QTILE + d) = *(const uint4*)(Ql + g);
    }
    __syncthreads();

    const int tq  = lane & 7;
    const int sel = lane >> 3;
    const int wq0 = wid * 16;
    uint32_t qfh[4][4], qfl[4][4];
    {
        const int arow = wq0 + tq + (sel & 1) * 8;
#pragma unroll
        for (int ks = 0; ks < 4; ks++) {
            const uint32_t a = sb + (uint32_t)(arow * AT_STR + (ks * 16 + (sel >> 1) * 8) * 2);
            LDSM4(qfh[ks][0], qfh[ks][1], qfh[ks][2], qfh[ks][3], a);
            LDSM4(qfl[ks][0], qfl[ks][1], qfl[ks][2], qfl[ks][3], a + AT_QTILE);
        }
    }

    float oacc[8][4];
#pragma unroll
    for (int nf = 0; nf < 8; nf++)
#pragma unroll
        for (int j = 0; j < 4; j++) oacc[nf][j] = 0.f;
    float m0 = -1e30f, m1 = -1e30f, l0 = 0.f, l1 = 0.f;

    const int NIT = SEQ / 64;
    for (int it = 0; it < NIT; it++) {
        if (it + 1 < NIT) { issue(it + 1); CP_WAIT1(); }
        else              { CP_WAIT0(); }
        __syncthreads();
        const uint32_t db = sb + AT_Q + (uint32_t)(it & 1) * AT_BUF;

        float sacc[8][4];
#pragma unroll
        for (int nf = 0; nf < 8; nf++)
#pragma unroll
            for (int j = 0; j < 4; j++) sacc[nf][j] = 0.f;

        // scores: QhKh + QlKh
#pragma unroll
        for (int ks = 0; ks < 4; ks++) {
            uint32_t bf[8][2];
#pragma unroll
            for (int p = 0; p < 4; p++) {
                const uint32_t a = db + (uint32_t)(((p * 16) + tq + (sel >> 1) * 8) * AT_STR
                                                 + (ks * 16 + (sel & 1) * 8) * 2);
                LDSM4(bf[2*p][0], bf[2*p][1], bf[2*p+1][0], bf[2*p+1][1], a);
            }
#pragma unroll
            for (int nf = 0; nf < 8; nf++) MMA16816(sacc[nf], qfh[ks], bf[nf]);
#pragma unroll
            for (int nf = 0; nf < 8; nf++) MMA16816(sacc[nf], qfl[ks], bf[nf]);
        }

#pragma unroll
        for (int nf = 0; nf < 8; nf++)
#pragma unroll
            for (int j = 0; j < 4; j++) sacc[nf][j] *= scale;

        float mx0 = -1e30f, mx1 = -1e30f;
#pragma unroll
        for (int nf = 0; nf < 8; nf++) {
            mx0 = fmaxf(mx0, fmaxf(sacc[nf][0], sacc[nf][1]));
            mx1 = fmaxf(mx1, fmaxf(sacc[nf][2], sacc[nf][3]));
        }
        mx0 = fmaxf(mx0, __shfl_xor_sync(0xffffffffu, mx0, 1));
        mx0 = fmaxf(mx0, __shfl_xor_sync(0xffffffffu, mx0, 2));
        mx1 = fmaxf(mx1, __shfl_xor_sync(0xffffffffu, mx1, 1));
        mx1 = fmaxf(mx1, __shfl_xor_sync(0xffffffffu, mx1, 2));

        const float mn0 = fmaxf(m0, mx0);
        const float mn1 = fmaxf(m1, mx1);
        const float al0 = __expf(m0 - mn0);
        const float al1 = __expf(m1 - mn1);
        m0 = mn0; m1 = mn1;

        uint32_t ph[4][4], pl[4][4];
        float sum0 = 0.f, sum1 = 0.f;
#pragma unroll
        for (int nf = 0; nf < 8; nf++) {
            const float p0 = __expf(sacc[nf][0] - m0);
            const float p1 = __expf(sacc[nf][1] - m0);
            const float p2 = __expf(sacc[nf][2] - m1);
            const float p3 = __expf(sacc[nf][3] - m1);
            sum0 += p0 + p1;
            sum1 += p2 + p3;
            const int kf = nf >> 1, hf = (nf & 1) * 2;
            const uint32_t h01 = packh2(p0, p1);
            const uint32_t h23 = packh2(p2, p3);
            ph[kf][hf]     = h01;
            ph[kf][hf + 1] = h23;
            const __half2 hb01 = *(const __half2*)&h01;
            const __half2 hb23 = *(const __half2*)&h23;
            pl[kf][hf]     = packh2(p0 - __half2float(hb01.x), p1 - __half2float(hb01.y));
            pl[kf][hf + 1] = packh2(p2 - __half2float(hb23.x), p3 - __half2float(hb23.y));
        }
        sum0 += __shfl_xor_sync(0xffffffffu, sum0, 1);
        sum0 += __shfl_xor_sync(0xffffffffu, sum0, 2);
        sum1 += __shfl_xor_sync(0xffffffffu, sum1, 1);
        sum1 += __shfl_xor_sync(0xffffffffu, sum1, 2);
        l0 = l0 * al0 + sum0;
        l1 = l1 * al1 + sum1;
#pragma unroll
        for (int nf = 0; nf < 8; nf++) {
            oacc[nf][0] *= al0; oacc[nf][1] *= al0;
            oacc[nf][2] *= al1; oacc[nf][3] *= al1;
        }

        // PV: PhVh + PlVh
#pragma unroll
        for (int kst = 0; kst < 4; kst++) {
            uint32_t vf[8][2];
#pragma unroll
            for (int p = 0; p < 4; p++) {
                const uint32_t a = db + AT_KVT
                    + (uint32_t)((kst * 16 + tq + (sel & 1) * 8) * AT_STR
                               + (p * 16 + (sel >> 1) * 8) * 2);
                LDSM4T(vf[2*p][0], vf[2*p][1], vf[2*p+1][0], vf[2*p+1][1], a);
            }
#pragma unroll
            for (int nf = 0; nf < 8; nf++) MMA16816(oacc[nf], ph[kst], vf[nf]);
#pragma unroll
            for (int nf = 0; nf < 8; nf++) MMA16816(oacc[nf], pl[kst], vf[nf]);
        }
        __syncthreads();
    }

    const float inv0 = 1.f / l0;
    const float inv1 = 1.f / l1;
    const int g  = lane >> 2;
    const int i2 = (lane & 3) << 1;
    const int row0 = q0 + wq0 + g;
    const int row1 = row0 + 8;
#pragma unroll
    for (int nf = 0; nf < 8; nf++) {
        const int coff = nf * 8 + i2;
        const float v0 = oacc[nf][0] * inv0;
        const float v1 = oacc[nf][1] * inv0;
        const float v2 = oacc[nf][2] * inv1;
        const float v3 = oacc[nf][3] * inv1;
        uint32_t hp = packh2(v0, v1);
        __half2 h2 = *(const __half2*)&hp;
        *(uint32_t*)&Ch[base + (size_t)row0 * DMODEL + coff] = hp;
        *(uint32_t*)&Cl[base + (size_t)row0 * DMODEL + coff] =
            packh2(v0 - __half2float(h2.x), v1 - __half2float(h2.y));
        hp = packh2(v2, v3);
        h2 = *(const __half2*)&hp;
        *(uint32_t*)&Ch[base + (size_t)row1 * DMODEL + coff] = hp;
        *(uint32_t*)&Cl[base + (size_t)row1 * DMODEL + coff] =
            packh2(v2 - __half2float(h2.x), v3 - __half2float(h2.y));
    }
}

// ============================================================================
// kernel_launch
// ============================================================================
extern "C" void kernel_launch(void* const* d_in, const int* in_sizes, int n_in,
                              void* d_out, int out_size)
{
    (void)in_sizes; (void)n_in; (void)out_size;

    const float* x  = (const float*)d_in[0];
    const float* We = (const float*)d_in[1];
    const float* be = (const float*)d_in[2];
    const float* Wq = (const float*)d_in[3];
    const float* bq = (const float*)d_in[4];
    const float* Wk = (const float*)d_in[5];
    const float* bk = (const float*)d_in[6];
    const float* Wv = (const float*)d_in[7];
    const float* bv = (const float*)d_in[8];
    const float* W0 = (const float*)d_in[9];
    const float* b0 = (const float*)d_in[10];
    const float* W1 = (const float*)d_in[11];
    const float* b1 = (const float*)d_in[12];
    const float* W2 = (const float*)d_in[13];
    const float* b2 = (const float*)d_in[14];
    float* out = (float*)d_out;

    float *e, *mha;
    __half *xh, *xl, *eh, *el, *qh, *ql, *kh, *vh;
    __half *ch, *cl, *mh, *ml, *hh, *hl, *Wh;
    cudaGetSymbolAddress((void**)&e,   g_e);
    cudaGetSymbolAddress((void**)&mha, g_mha);
    cudaGetSymbolAddress((void**)&xh,  g_xh);
    cudaGetSymbolAddress((void**)&xl,  g_xl);
    cudaGetSymbolAddress((void**)&eh,  g_eh);
    cudaGetSymbolAddress((void**)&el,  g_el);
    cudaGetSymbolAddress((void**)&qh,  g_qh);
    cudaGetSymbolAddress((void**)&ql,  g_ql);
    cudaGetSymbolAddress((void**)&kh,  g_kh);
    cudaGetSymbolAddress((void**)&vh,  g_vh);
    cudaGetSymbolAddress((void**)&ch,  g_ch);
    cudaGetSymbolAddress((void**)&cl,  g_cl);
    cudaGetSymbolAddress((void**)&mh,  g_mh);
    cudaGetSymbolAddress((void**)&ml,  g_ml);
    cudaGetSymbolAddress((void**)&hh,  g_hh);
    cudaGetSymbolAddress((void**)&hl,  g_hl);
    cudaGetSymbolAddress((void**)&Wh,  g_Wh);

    cudaFuncSetAttribute(gemm_mma, cudaFuncAttributeMaxDynamicSharedMemorySize, GEMM_SMEM);
    cudaFuncSetAttribute(gemm_qkv, cudaFuncAttributeMaxDynamicSharedMemorySize, GEMM_SMEM);
    cudaFuncSetAttribute(attn_mma, cudaFuncAttributeMaxDynamicSharedMemorySize, AT_SMEM);

    // all weight transposes+casts in one launch; x split
    wsplit_all<<<dim3(32, 32, 7), dim3(32, 8)>>>(We, Wq, Wk, Wv, W0, W1, W2, Wh);
    xsplit<<<MROWS * DIN / 512, 256>>>(x, xh, xl);

    __half* Wqh = Wh + WSZ_E;
    __half* W0h = Wqh + 3*WSZ;
    __half* W1h = W0h + WSZ;
    __half* W2h = W1h + WSZ;

    const dim3 gg(4, 32);   // (N/256, M/128)
    // e = x @ We + be  (fp32 + hi/lo)
    gemm_mma<<<gg, 256, GEMM_SMEM>>>(xh, xl, Wh, be, nullptr, e, eh, el, DIN, 0);
    // q,k,v fused (q: hi/lo; k,v: hi)
    gemm_qkv<<<dim3(12, 32), 256, GEMM_SMEM>>>(eh, el, Wqh, bq, bk, bv, qh, ql, kh, vh);
    // attention -> ctx (fp16 hi/lo)
    attn_mma<<<dim3(SEQ / 128, 32), 256, AT_SMEM>>>(qh, ql, kh, vh, ch, cl);
    // mha = e + ctx @ W0 + b0  (fp32 + hi/lo)
    gemm_mma<<<gg, 256, GEMM_SMEM>>>(ch, cl, W0h, b0, e, mha, mh, ml, DMODEL, 0);
    // h1 = relu(mha @ W1 + b1)  (hi/lo only)
    gemm_mma<<<gg, 256, GEMM_SMEM>>>(mh, ml, W1h, b1, nullptr, nullptr, hh, hl, DMODEL, 1);
    // out = mha + h1 @ W2 + b2  (fp32)
    gemm_mma<<<gg, 256, GEMM_SMEM>>>(hh, hl, W2h, b2, mha, out, nullptr, nullptr, DMODEL, 0);
}

// round 15
// speedup vs baseline: 1.5085x; 1.0728x over previous
#include <cuda_runtime.h>
#include <cuda_fp16.h>
#include <cstdint>

#define MROWS  4096
#define DMODEL 1024
#define DIN    512
#define NHEAD  16
#define SEQ    2048

// ---------------- scratch (allocation-free) ----------------
__device__ __align__(128) __half g_xh[MROWS*DIN],    g_xl[MROWS*DIN];
__device__ __align__(128) __half g_eh[MROWS*DMODEL], g_el[MROWS*DMODEL];
__device__ __align__(128) __half g_qh[MROWS*DMODEL], g_ql[MROWS*DMODEL];
__device__ __align__(128) __half g_kh[MROWS*DMODEL];
__device__ __align__(128) __half g_vh[MROWS*DMODEL];
__device__ __align__(128) __half g_ch[MROWS*DMODEL], g_cl[MROWS*DMODEL];
__device__ __align__(128) __half g_mh[MROWS*DMODEL], g_ml[MROWS*DMODEL];
__device__ __align__(128) __half g_hh[MROWS*DMODEL], g_hl[MROWS*DMODEL];
#define WSZ_E (DMODEL*DIN)
#define WSZ   (DMODEL*DMODEL)
__device__ __align__(128) __half g_Wh[WSZ_E + 6*WSZ];

// ---------------- helpers ----------------
__device__ __forceinline__ uint32_t smem_u32(const void* p) {
    uint32_t a;
    asm("{ .reg .u64 t; cvta.to.shared.u64 t, %1; cvt.u32.u64 %0, t; }" : "=r"(a) : "l"(p));
    return a;
}

#define CP_ASYNC16(dst, src) \
    asm volatile("cp.async.cg.shared.global [%0], [%1], 16;" :: "r"(dst), "l"(src) : "memory")
#define CP_COMMIT()  asm volatile("cp.async.commit_group;" ::: "memory")
#define CP_WAIT1()   asm volatile("cp.async.wait_group 1;" ::: "memory")
#define CP_WAIT0()   asm volatile("cp.async.wait_group 0;" ::: "memory")

#define LDSM4(r0, r1, r2, r3, a) \
    asm volatile("ldmatrix.sync.aligned.m8n8.x4.shared.b16 {%0,%1,%2,%3}, [%4];" \
                 : "=r"(r0), "=r"(r1), "=r"(r2), "=r"(r3) : "r"(a))
#define LDSM4T(r0, r1, r2, r3, a) \
    asm volatile("ldmatrix.sync.aligned.m8n8.x4.trans.shared.b16 {%0,%1,%2,%3}, [%4];" \
                 : "=r"(r0), "=r"(r1), "=r"(r2), "=r"(r3) : "r"(a))

#define MMA16816(d, a, b) \
    asm volatile("mma.sync.aligned.m16n8k16.row.col.f32.f16.f16.f32 " \
                 "{%0,%1,%2,%3}, {%4,%5,%6,%7}, {%8,%9}, {%0,%1,%2,%3};" \
                 : "+f"((d)[0]), "+f"((d)[1]), "+f"((d)[2]), "+f"((d)[3]) \
                 : "r"((a)[0]), "r"((a)[1]), "r"((a)[2]), "r"((a)[3]), \
                   "r"((b)[0]), "r"((b)[1]))

__device__ __forceinline__ uint32_t packh2(float a, float b) {
    __half2 t;
    t.x = __float2half_rn(a);
    t.y = __float2half_rn(b);
    return *(uint32_t*)&t;
}

// ============================================================================
// Fused weight transpose + fp16 cast for all 7 weights (grid.z selects).
// ============================================================================
__global__ void __launch_bounds__(256)
wsplit_all(const float* __restrict__ We, const float* __restrict__ Wq,
           const float* __restrict__ Wk, const float* __restrict__ Wv,
           const float* __restrict__ W0, const float* __restrict__ W1,
           const float* __restrict__ W2, __half* __restrict__ ThB)
{
    const int z = blockIdx.z;
    const int K = (z == 0) ? DIN : DMODEL;
    if ((int)blockIdx.y * 32 >= K) return;
    const float* W = (z == 0) ? We : (z == 1) ? Wq : (z == 2) ? Wk :
                     (z == 3) ? Wv : (z == 4) ? W0 : (z == 5) ? W1 : W2;
    const size_t off = (z == 0) ? 0 : (size_t)WSZ_E + (size_t)(z - 1) * WSZ;
    __half* Th = ThB + off;

    __shared__ float t[32][33];
    const int tx = threadIdx.x, ty = threadIdx.y;
    const int n = blockIdx.x * 32 + tx;
#pragma unroll
    for (int i = 0; i < 4; i++) {
        const int k = blockIdx.y * 32 + ty + i * 8;
        t[ty + i * 8][tx] = W[(size_t)k * DMODEL + n];
    }
    __syncthreads();
    const int k2 = blockIdx.y * 32 + tx;
#pragma unroll
    for (int i = 0; i < 4; i++) {
        const int n2 = blockIdx.x * 32 + ty + i * 8;
        Th[(size_t)n2 * K + k2] = __float2half_rn(t[tx][ty + i * 8]);
    }
}

__global__ void __launch_bounds__(256)
xsplit(const float* __restrict__ X, __half* __restrict__ H, __half* __restrict__ L)
{
    const int i = blockIdx.x * 256 + threadIdx.x;
    const float2 v = ((const float2*)X)[i];
    const __half hx = __float2half_rn(v.x);
    const __half hy = __float2half_rn(v.y);
    __half2 hp, lp;
    hp.x = hx; hp.y = hy;
    lp.x = __float2half_rn(v.x - __half2float(hx));
    lp.y = __float2half_rn(v.y - __half2float(hy));
    ((__half2*)H)[i] = hp;
    ((__half2*)L)[i] = lp;
}

// ============================================================================
// GEMM: CTA tile 128x256, BK=64 (row stride 144B, conflict-free ldmatrix),
// 256 threads = 8 warps (2m x 4n), warp tile 64x64.
// fp16 2-pass: C = Ah*Wh + Al*Wh.  Double-buffered cp.async.
// Per buffer: Ah,Al 128x144B (18432 ea) + Bh 256x144B (36864) = 73728; x2.
// ============================================================================
#define GA_TILE 18432
#define GB_TILE 36864
#define GBUF    (2*GA_TILE + GB_TILE)     // 73728
#define GEMM_SMEM (2*GBUF)                // 147456

#define GEMM_MAINLOOP(K_)                                                       \
    float acc[4][8][4];                                                         \
    _Pragma("unroll")                                                           \
    for (int mf = 0; mf < 4; mf++)                                              \
        _Pragma("unroll")                                                       \
        for (int nf = 0; nf < 8; nf++)                                          \
            _Pragma("unroll")                                                   \
            for (int j = 0; j < 4; j++) acc[mf][nf][j] = 0.f;                   \
    const int NIT = (K_) >> 6;                                                  \
    auto issue = [&](int it) {                                                  \
        const int k0 = it << 6;                                                 \
        const uint32_t db = sb + (uint32_t)(it & 1) * GBUF;                     \
        _Pragma("unroll")                                                       \
        for (int t = 0; t < 2; t++) {                                           \
            _Pragma("unroll")                                                   \
            for (int s = 0; s < 4; s++) {                                       \
                const int id = tid + s * 256;                                   \
                const int row = id >> 3, c = id & 7;                            \
                const __half* g = srcs[t] + (size_t)row * (K_) + k0 + c * 8;    \
                CP_ASYNC16(db + (uint32_t)t * GA_TILE                           \
                           + (uint32_t)(row * 144 + c * 16), g);                \
            }                                                                   \
        }                                                                       \
        _Pragma("unroll")                                                       \
        for (int s = 0; s < 8; s++) {                                           \
            const int id = tid + s * 256;                                       \
            const int row = id >> 3, c = id & 7;                                \
            const __half* g = srcs[2] + (size_t)row * (K_) + k0 + c * 8;        \
            CP_ASYNC16(db + 2u * GA_TILE                                        \
                       + (uint32_t)(row * 144 + c * 16), g);                    \
        }                                                                       \
        CP_COMMIT();                                                            \
    };                                                                          \
    issue(0);                                                                   \
    const int a_r  = lane & 15;                                                 \
    const int a_kh = lane >> 4;                                                 \
    const int b_nl = (lane & 7) + ((lane >> 4) << 3);                           \
    const int b_kh = (lane >> 3) & 1;                                           \
    for (int it = 0; it < NIT; it++) {                                          \
        if (it + 1 < NIT) { issue(it + 1); CP_WAIT1(); }                        \
        else              { CP_WAIT0(); }                                       \
        __syncthreads();                                                        \
        const uint32_t db = sb + (uint32_t)(it & 1) * GBUF;                     \
        _Pragma("unroll")                                                       \
        for (int ks = 0; ks < 4; ks++) {                                        \
            uint32_t ah[4][4], al[4][4], bh[8][2];                              \
            _Pragma("unroll")                                                   \
            for (int mf = 0; mf < 4; mf++) {                                    \
                const uint32_t aoff = (uint32_t)((wm * 64 + mf * 16 + a_r) * 144 \
                                               + (ks * 16 + a_kh * 8) * 2);     \
                LDSM4(ah[mf][0], ah[mf][1], ah[mf][2], ah[mf][3], db + aoff);   \
                LDSM4(al[mf][0], al[mf][1], al[mf][2], al[mf][3],               \
                      db + GA_TILE + aoff);                                     \
            }                                                                   \
            _Pragma("unroll")                                                   \
            for (int nf2 = 0; nf2 < 4; nf2++) {                                 \
                const uint32_t boff = (uint32_t)((wn * 64 + nf2 * 16 + b_nl) * 144 \
                                               + (ks * 16 + b_kh * 8) * 2);     \
                LDSM4(bh[2*nf2][0], bh[2*nf2][1], bh[2*nf2+1][0], bh[2*nf2+1][1], \
                      db + 2u * GA_TILE + boff);                                \
            }                                                                   \
            _Pragma("unroll")                                                   \
            for (int mf = 0; mf < 4; mf++)                                      \
                _Pragma("unroll")                                               \
                for (int nf = 0; nf < 8; nf++)                                  \
                    MMA16816(acc[mf][nf], ah[mf], bh[nf]);                      \
            _Pragma("unroll")                                                   \
            for (int mf = 0; mf < 4; mf++)                                      \
                _Pragma("unroll")                                               \
                for (int nf = 0; nf < 8; nf++)                                  \
                    MMA16816(acc[mf][nf], al[mf], bh[nf]);                      \
        }                                                                       \
        __syncthreads();                                                        \
    }

// ---- generic GEMM: hi/lo residual, fp32 and/or fp16 hi/lo out, bias/relu ----
__global__ void __launch_bounds__(256)
gemm_mma(const __half* __restrict__ Ah, const __half* __restrict__ Al,
         const __half* __restrict__ Bh,
         const float* __restrict__ bias,
         const __half* __restrict__ resh, const __half* __restrict__ resl,
         float* __restrict__ Cf, __half* __restrict__ Ch,
         __half* __restrict__ Cl, int K, int relu)
{
    extern __shared__ char smem[];
    const uint32_t sb = smem_u32(smem);
    const int tid  = threadIdx.x;
    const int wid  = tid >> 5;
    const int lane = tid & 31;
    const int wm = wid >> 2;
    const int wn = wid & 3;
    const int m0 = blockIdx.y * 128;
    const int n0 = blockIdx.x * 256;

    const __half* srcs[3] = {
        Ah + (size_t)m0 * K, Al + (size_t)m0 * K, Bh + (size_t)n0 * K };

    GEMM_MAINLOOP(K)

    const int g  = lane >> 2;
    const int i2 = (lane & 3) << 1;
#pragma unroll
    for (int mf = 0; mf < 4; mf++) {
        const int rowa = m0 + wm * 64 + mf * 16 + g;
        const int rowb = rowa + 8;
#pragma unroll
        for (int nf = 0; nf < 8; nf++) {
            const int col = n0 + wn * 64 + nf * 8 + i2;
            const float2 b2 = *(const float2*)&bias[col];
            float v0 = acc[mf][nf][0] + b2.x;
            float v1 = acc[mf][nf][1] + b2.y;
            float v2 = acc[mf][nf][2] + b2.x;
            float v3 = acc[mf][nf][3] + b2.y;
            if (relu) {
                v0 = fmaxf(v0, 0.f); v1 = fmaxf(v1, 0.f);
                v2 = fmaxf(v2, 0.f); v3 = fmaxf(v3, 0.f);
            }
            if (resh) {
                const __half2 ha = *(const __half2*)&resh[(size_t)rowa * DMODEL + col];
                const __half2 la = *(const __half2*)&resl[(size_t)rowa * DMODEL + col];
                const __half2 hb = *(const __half2*)&resh[(size_t)rowb * DMODEL + col];
                const __half2 lb = *(const __half2*)&resl[(size_t)rowb * DMODEL + col];
                v0 += __half2float(ha.x) + __half2float(la.x);
                v1 += __half2float(ha.y) + __half2float(la.y);
                v2 += __half2float(hb.x) + __half2float(lb.x);
                v3 += __half2float(hb.y) + __half2float(lb.y);
            }
            if (Cf) {
                *(float2*)&Cf[(size_t)rowa * DMODEL + col] = make_float2(v0, v1);
                *(float2*)&Cf[(size_t)rowb * DMODEL + col] = make_float2(v2, v3);
            }
            if (Ch) {
                uint32_t hp = packh2(v0, v1);
                const __half2 h2a = *(const __half2*)&hp;
                uint32_t lp = packh2(v0 - __half2float(h2a.x), v1 - __half2float(h2a.y));
                *(uint32_t*)&Ch[(size_t)rowa * DMODEL + col] = hp;
                *(uint32_t*)&Cl[(size_t)rowa * DMODEL + col] = lp;
                hp = packh2(v2, v3);
                const __half2 h2b = *(const __half2*)&hp;
                lp = packh2(v2 - __half2float(h2b.x), v3 - __half2float(h2b.y));
                *(uint32_t*)&Ch[(size_t)rowb * DMODEL + col] = hp;
                *(uint32_t*)&Cl[(size_t)rowb * DMODEL + col] = lp;
            }
        }
    }
}

// ---- fused QKV GEMM: N=3072 (Wq|Wk|Wv contiguous). q gets hi+lo; k,v hi only.
__global__ void __launch_bounds__(256)
gemm_qkv(const __half* __restrict__ Ah, const __half* __restrict__ Al,
         const __half* __restrict__ Bh,
         const float* __restrict__ bq, const float* __restrict__ bk,
         const float* __restrict__ bv,
         __half* __restrict__ qh, __half* __restrict__ ql,
         __half* __restrict__ kh, __half* __restrict__ vh)
{
    extern __shared__ char smem[];
    const uint32_t sb = smem_u32(smem);
    const int tid  = threadIdx.x;
    const int wid  = tid >> 5;
    const int lane = tid & 31;
    const int wm = wid >> 2;
    const int wn = wid & 3;
    const int m0 = blockIdx.y * 128;
    const int n0 = blockIdx.x * 256;      // global n in [0, 3072)
    const int K = DMODEL;

    const __half* srcs[3] = {
        Ah + (size_t)m0 * K, Al + (size_t)m0 * K, Bh + (size_t)n0 * K };

    GEMM_MAINLOOP(K)

    const int selq = n0 >> 10;
    const int nc0  = n0 & 1023;
    const float* bias = (selq == 0) ? bq : (selq == 1) ? bk : bv;
    __half* Oh = (selq == 0) ? qh : (selq == 1) ? kh : vh;
    __half* Ol = (selq == 0) ? ql : nullptr;

    const int g  = lane >> 2;
    const int i2 = (lane & 3) << 1;
#pragma unroll
    for (int mf = 0; mf < 4; mf++) {
        const int rowa = m0 + wm * 64 + mf * 16 + g;
        const int rowb = rowa + 8;
#pragma unroll
        for (int nf = 0; nf < 8; nf++) {
            const int col = nc0 + wn * 64 + nf * 8 + i2;
            const float2 b2 = *(const float2*)&bias[col];
            const float v0 = acc[mf][nf][0] + b2.x;
            const float v1 = acc[mf][nf][1] + b2.y;
            const float v2 = acc[mf][nf][2] + b2.x;
            const float v3 = acc[mf][nf][3] + b2.y;
            const uint32_t hpa = packh2(v0, v1);
            const uint32_t hpb = packh2(v2, v3);
            *(uint32_t*)&Oh[(size_t)rowa * DMODEL + col] = hpa;
            *(uint32_t*)&Oh[(size_t)rowb * DMODEL + col] = hpb;
            if (Ol) {
                const __half2 h2a = *(const __half2*)&hpa;
                const __half2 h2b = *(const __half2*)&hpb;
                *(uint32_t*)&Ol[(size_t)rowa * DMODEL + col] =
                    packh2(v0 - __half2float(h2a.x), v1 - __half2float(h2a.y));
                *(uint32_t*)&Ol[(size_t)rowb * DMODEL + col] =
                    packh2(v2 - __half2float(h2b.x), v3 - __half2float(h2b.y));
            }
        }
    }
}

// ============================================================================
// Tensor-core flash attention, fp16 2-pass (unchanged from R14 WIN).
// ============================================================================
#define AT_STR    144
#define AT_QTILE  (128*AT_STR)
#define AT_KVT    (64*AT_STR)
#define AT_BUF    (2*AT_KVT)
#define AT_Q      (2*AT_QTILE)
#define AT_SMEM   (AT_Q + 2*AT_BUF)     // 73728

__global__ void __launch_bounds__(256, 1)
attn_mma(const __half* __restrict__ Qh, const __half* __restrict__ Ql,
         const __half* __restrict__ Kh, const __half* __restrict__ Vh,
         __half* __restrict__ Ch, __half* __restrict__ Cl)
{
    extern __shared__ char smem[];
    const uint32_t sb = smem_u32(smem);
    const int tid  = threadIdx.x;
    const int wid  = tid >> 5;
    const int lane = tid & 31;
    const int q0   = blockIdx.x * 128;
    const int bh   = blockIdx.y;
    const int b    = bh >> 4;
    const int h    = bh & (NHEAD - 1);
    const size_t base = (size_t)b * SEQ * DMODEL + (size_t)h * 64;
    const float scale = 0.125f;

    const __half* kvs[2] = { Kh + base, Vh + base };

    auto issue = [&](int it) {
        const int kv0 = it << 6;
        const uint32_t db = sb + AT_Q + (uint32_t)(it & 1) * AT_BUF;
#pragma unroll
        for (int t = 0; t < 2; t++) {
#pragma unroll
            for (int s = 0; s < 2; s++) {
                const int id = tid + s * 256;
                const int row = id >> 3, c16 = id & 7;
                const __half* g = kvs[t] + (size_t)(kv0 + row) * DMODEL + c16 * 8;
                const uint32_t d = db + (uint32_t)t * AT_KVT + (uint32_t)(row * AT_STR + c16 * 16);
                CP_ASYNC16(d, g);
            }
        }
        CP_COMMIT();
    };

    issue(0);

#pragma unroll
    for (int s = 0; s < 4; s++) {
        const int id = tid + s * 256;
        const int row = id >> 3, c16 = id & 7;
        const size_t g = base + (size_t)(q0 + row) * DMODEL + c16 * 8;
        const uint32_t d = (uint32_t)(row * AT_STR + c16 * 16);
        *(uint4*)(smem + d)            = *(const uint4*)(Qh + g);
        *(uint4*)(smem + AT_QTILE + d) = *(const uint4*)(Ql + g);
    }
    __syncthreads();

    const int tq  = lane & 7;
    const int sel = lane >> 3;
    const int wq0 = wid * 16;
    uint32_t qfh[4][4], qfl[4][4];
    {
        const int arow = wq0 + tq + (sel & 1) * 8;
#pragma unroll
        for (int ks = 0; ks < 4; ks++) {
            const uint32_t a = sb + (uint32_t)(arow * AT_STR + (ks * 16 + (sel >> 1) * 8) * 2);
            LDSM4(qfh[ks][0], qfh[ks][1], qfh[ks][2], qfh[ks][3], a);
            LDSM4(qfl[ks][0], qfl[ks][1], qfl[ks][2], qfl[ks][3], a + AT_QTILE);
        }
    }

    float oacc[8][4];
#pragma unroll
    for (int nf = 0; nf < 8; nf++)
#pragma unroll
        for (int j = 0; j < 4; j++) oacc[nf][j] = 0.f;
    float m0 = -1e30f, m1 = -1e30f, l0 = 0.f, l1 = 0.f;

    const int NIT = SEQ / 64;
    for (int it = 0; it < NIT; it++) {
        if (it + 1 < NIT) { issue(it + 1); CP_WAIT1(); }
        else              { CP_WAIT0(); }
        __syncthreads();
        const uint32_t db = sb + AT_Q + (uint32_t)(it & 1) * AT_BUF;

        float sacc[8][4];
#pragma unroll
        for (int nf = 0; nf < 8; nf++)
#pragma unroll
            for (int j = 0; j < 4; j++) sacc[nf][j] = 0.f;

#pragma unroll
        for (int ks = 0; ks < 4; ks++) {
            uint32_t bf[8][2];
#pragma unroll
            for (int p = 0; p < 4; p++) {
                const uint32_t a = db + (uint32_t)(((p * 16) + tq + (sel >> 1) * 8) * AT_STR
                                                 + (ks * 16 + (sel & 1) * 8) * 2);
                LDSM4(bf[2*p][0], bf[2*p][1], bf[2*p+1][0], bf[2*p+1][1], a);
            }
#pragma unroll
            for (int nf = 0; nf < 8; nf++) MMA16816(sacc[nf], qfh[ks], bf[nf]);
#pragma unroll
            for (int nf = 0; nf < 8; nf++) MMA16816(sacc[nf], qfl[ks], bf[nf]);
        }

#pragma unroll
        for (int nf = 0; nf < 8; nf++)
#pragma unroll
            for (int j = 0; j < 4; j++) sacc[nf][j] *= scale;

        float mx0 = -1e30f, mx1 = -1e30f;
#pragma unroll
        for (int nf = 0; nf < 8; nf++) {
            mx0 = fmaxf(mx0, fmaxf(sacc[nf][0], sacc[nf][1]));
            mx1 = fmaxf(mx1, fmaxf(sacc[nf][2], sacc[nf][3]));
        }
        mx0 = fmaxf(mx0, __shfl_xor_sync(0xffffffffu, mx0, 1));
        mx0 = fmaxf(mx0, __shfl_xor_sync(0xffffffffu, mx0, 2));
        mx1 = fmaxf(mx1, __shfl_xor_sync(0xffffffffu, mx1, 1));
        mx1 = fmaxf(mx1, __shfl_xor_sync(0xffffffffu, mx1, 2));

        const float mn0 = fmaxf(m0, mx0);
        const float mn1 = fmaxf(m1, mx1);
        const float al0 = __expf(m0 - mn0);
        const float al1 = __expf(m1 - mn1);
        m0 = mn0; m1 = mn1;

        uint32_t ph[4][4], pl[4][4];
        float sum0 = 0.f, sum1 = 0.f;
#pragma unroll
        for (int nf = 0; nf < 8; nf++) {
            const float p0 = __expf(sacc[nf][0] - m0);
            const float p1 = __expf(sacc[nf][1] - m0);
            const float p2 = __expf(sacc[nf][2] - m1);
            const float p3 = __expf(sacc[nf][3] - m1);
            sum0 += p0 + p1;
            sum1 += p2 + p3;
            const int kf = nf >> 1, hf = (nf & 1) * 2;
            const uint32_t h01 = packh2(p0, p1);
            const uint32_t h23 = packh2(p2, p3);
            ph[kf][hf]     = h01;
            ph[kf][hf + 1] = h23;
            const __half2 hb01 = *(const __half2*)&h01;
            const __half2 hb23 = *(const __half2*)&h23;
            pl[kf][hf]     = packh2(p0 - __half2float(hb01.x), p1 - __half2float(hb01.y));
            pl[kf][hf + 1] = packh2(p2 - __half2float(hb23.x), p3 - __half2float(hb23.y));
        }
        sum0 += __shfl_xor_sync(0xffffffffu, sum0, 1);
        sum0 += __shfl_xor_sync(0xffffffffu, sum0, 2);
        sum1 += __shfl_xor_sync(0xffffffffu, sum1, 1);
        sum1 += __shfl_xor_sync(0xffffffffu, sum1, 2);
        l0 = l0 * al0 + sum0;
        l1 = l1 * al1 + sum1;
#pragma unroll
        for (int nf = 0; nf < 8; nf++) {
            oacc[nf][0] *= al0; oacc[nf][1] *= al0;
            oacc[nf][2] *= al1; oacc[nf][3] *= al1;
        }

#pragma unroll
        for (int kst = 0; kst < 4; kst++) {
            uint32_t vf[8][2];
#pragma unroll
            for (int p = 0; p < 4; p++) {
                const uint32_t a = db + AT_KVT
                    + (uint32_t)((kst * 16 + tq + (sel & 1) * 8) * AT_STR
                               + (p * 16 + (sel >> 1) * 8) * 2);
                LDSM4T(vf[2*p][0], vf[2*p][1], vf[2*p+1][0], vf[2*p+1][1], a);
            }
#pragma unroll
            for (int nf = 0; nf < 8; nf++) MMA16816(oacc[nf], ph[kst], vf[nf]);
#pragma unroll
            for (int nf = 0; nf < 8; nf++) MMA16816(oacc[nf], pl[kst], vf[nf]);
        }
        __syncthreads();
    }

    const float inv0 = 1.f / l0;
    const float inv1 = 1.f / l1;
    const int g  = lane >> 2;
    const int i2 = (lane & 3) << 1;
    const int row0 = q0 + wq0 + g;
    const int row1 = row0 + 8;
#pragma unroll
    for (int nf = 0; nf < 8; nf++) {
        const int coff = nf * 8 + i2;
        const float v0 = oacc[nf][0] * inv0;
        const float v1 = oacc[nf][1] * inv0;
        const float v2 = oacc[nf][2] * inv1;
        const float v3 = oacc[nf][3] * inv1;
        uint32_t hp = packh2(v0, v1);
        __half2 h2 = *(const __half2*)&hp;
        *(uint32_t*)&Ch[base + (size_t)row0 * DMODEL + coff] = hp;
        *(uint32_t*)&Cl[base + (size_t)row0 * DMODEL + coff] =
            packh2(v0 - __half2float(h2.x), v1 - __half2float(h2.y));
        hp = packh2(v2, v3);
        h2 = *(const __half2*)&hp;
        *(uint32_t*)&Ch[base + (size_t)row1 * DMODEL + coff] = hp;
        *(uint32_t*)&Cl[base + (size_t)row1 * DMODEL + coff] =
            packh2(v2 - __half2float(h2.x), v3 - __half2float(h2.y));
    }
}

// ============================================================================
// kernel_launch
// ============================================================================
extern "C" void kernel_launch(void* const* d_in, const int* in_sizes, int n_in,
                              void* d_out, int out_size)
{
    (void)in_sizes; (void)n_in; (void)out_size;

    const float* x  = (const float*)d_in[0];
    const float* We = (const float*)d_in[1];
    const float* be = (const float*)d_in[2];
    const float* Wq = (const float*)d_in[3];
    const float* bq = (const float*)d_in[4];
    const float* Wk = (const float*)d_in[5];
    const float* bk = (const float*)d_in[6];
    const float* Wv = (const float*)d_in[7];
    const float* bv = (const float*)d_in[8];
    const float* W0 = (const float*)d_in[9];
    const float* b0 = (const float*)d_in[10];
    const float* W1 = (const float*)d_in[11];
    const float* b1 = (const float*)d_in[12];
    const float* W2 = (const float*)d_in[13];
    const float* b2 = (const float*)d_in[14];
    float* out = (float*)d_out;

    __half *xh, *xl, *eh, *el, *qh, *ql, *kh, *vh;
    __half *ch, *cl, *mh, *ml, *hh, *hl, *Wh;
    cudaGetSymbolAddress((void**)&xh,  g_xh);
    cudaGetSymbolAddress((void**)&xl,  g_xl);
    cudaGetSymbolAddress((void**)&eh,  g_eh);
    cudaGetSymbolAddress((void**)&el,  g_el);
    cudaGetSymbolAddress((void**)&qh,  g_qh);
    cudaGetSymbolAddress((void**)&ql,  g_ql);
    cudaGetSymbolAddress((void**)&kh,  g_kh);
    cudaGetSymbolAddress((void**)&vh,  g_vh);
    cudaGetSymbolAddress((void**)&ch,  g_ch);
    cudaGetSymbolAddress((void**)&cl,  g_cl);
    cudaGetSymbolAddress((void**)&mh,  g_mh);
    cudaGetSymbolAddress((void**)&ml,  g_ml);
    cudaGetSymbolAddress((void**)&hh,  g_hh);
    cudaGetSymbolAddress((void**)&hl,  g_hl);
    cudaGetSymbolAddress((void**)&Wh,  g_Wh);

    cudaFuncSetAttribute(gemm_mma, cudaFuncAttributeMaxDynamicSharedMemorySize, GEMM_SMEM);
    cudaFuncSetAttribute(gemm_qkv, cudaFuncAttributeMaxDynamicSharedMemorySize, GEMM_SMEM);
    cudaFuncSetAttribute(attn_mma, cudaFuncAttributeMaxDynamicSharedMemorySize, AT_SMEM);

    // all weight transposes+casts in one launch; x split
    wsplit_all<<<dim3(32, 32, 7), dim3(32, 8)>>>(We, Wq, Wk, Wv, W0, W1, W2, Wh);
    xsplit<<<MROWS * DIN / 512, 256>>>(x, xh, xl);

    __half* Wqh = Wh + WSZ_E;
    __half* W0h = Wqh + 3*WSZ;
    __half* W1h = W0h + WSZ;
    __half* W2h = W1h + WSZ;

    const dim3 gg(4, 32);   // (N/256, M/128)
    // e = x @ We + be  (hi/lo only; residual reconstructed from eh+el later)
    gemm_mma<<<gg, 256, GEMM_SMEM>>>(xh, xl, Wh, be, nullptr, nullptr,
                                     nullptr, eh, el, DIN, 0);
    // q,k,v fused (q: hi/lo; k,v: hi)
    gemm_qkv<<<dim3(12, 32), 256, GEMM_SMEM>>>(eh, el, Wqh, bq, bk, bv, qh, ql, kh, vh);
    // attention -> ctx (fp16 hi/lo)
    attn_mma<<<dim3(SEQ / 128, 32), 256, AT_SMEM>>>(qh, ql, kh, vh, ch, cl);
    // mha = (eh+el) + ctx @ W0 + b0  (hi/lo only)
    gemm_mma<<<gg, 256, GEMM_SMEM>>>(ch, cl, W0h, b0, eh, el,
                                     nullptr, mh, ml, DMODEL, 0);
    // h1 = relu(mha @ W1 + b1)  (hi/lo only)
    gemm_mma<<<gg, 256, GEMM_SMEM>>>(mh, ml, W1h, b1, nullptr, nullptr,
                                     nullptr, hh, hl, DMODEL, 1);
    // out = (mh+ml) + h1 @ W2 + b2  (fp32)
    gemm_mma<<<gg, 256, GEMM_SMEM>>>(hh, hl, W2h, b2, mh, ml,
                                     out, nullptr, nullptr, DMODEL, 0);
}

// round 16
// speedup vs baseline: 1.6191x; 1.0733x over previous
#include <cuda_runtime.h>
#include <cuda_fp16.h>
#include <cstdint>

#define MROWS  4096
#define DMODEL 1024
#define DIN    512
#define NHEAD  16
#define SEQ    2048

// ---------------- scratch (allocation-free) ----------------
__device__ __align__(128) __half g_xh[MROWS*DIN],    g_xl[MROWS*DIN];
__device__ __align__(128) __half g_eh[MROWS*DMODEL], g_el[MROWS*DMODEL];
__device__ __align__(128) __half g_qh[MROWS*DMODEL], g_ql[MROWS*DMODEL];
__device__ __align__(128) __half g_kh[MROWS*DMODEL];
__device__ __align__(128) __half g_vh[MROWS*DMODEL];
__device__ __align__(128) __half g_ch[MROWS*DMODEL], g_cl[MROWS*DMODEL];
__device__ __align__(128) __half g_mh[MROWS*DMODEL], g_ml[MROWS*DMODEL];
__device__ __align__(128) __half g_hh[MROWS*DMODEL], g_hl[MROWS*DMODEL];
#define WSZ_E (DMODEL*DIN)
#define WSZ   (DMODEL*DMODEL)
__device__ __align__(128) __half g_Wh[WSZ_E + 6*WSZ];

// ---------------- helpers ----------------
__device__ __forceinline__ uint32_t smem_u32(const void* p) {
    uint32_t a;
    asm("{ .reg .u64 t; cvta.to.shared.u64 t, %1; cvt.u32.u64 %0, t; }" : "=r"(a) : "l"(p));
    return a;
}

#define CP_ASYNC16(dst, src) \
    asm volatile("cp.async.cg.shared.global [%0], [%1], 16;" :: "r"(dst), "l"(src) : "memory")
#define CP_COMMIT()  asm volatile("cp.async.commit_group;" ::: "memory")
#define CP_WAIT1()   asm volatile("cp.async.wait_group 1;" ::: "memory")
#define CP_WAIT0()   asm volatile("cp.async.wait_group 0;" ::: "memory")

#define LDSM4(r0, r1, r2, r3, a) \
    asm volatile("ldmatrix.sync.aligned.m8n8.x4.shared.b16 {%0,%1,%2,%3}, [%4];" \
                 : "=r"(r0), "=r"(r1), "=r"(r2), "=r"(r3) : "r"(a))
#define LDSM4T(r0, r1, r2, r3, a) \
    asm volatile("ldmatrix.sync.aligned.m8n8.x4.trans.shared.b16 {%0,%1,%2,%3}, [%4];" \
                 : "=r"(r0), "=r"(r1), "=r"(r2), "=r"(r3) : "r"(a))

#define MMA16816(d, a, b) \
    asm volatile("mma.sync.aligned.m16n8k16.row.col.f32.f16.f16.f32 " \
                 "{%0,%1,%2,%3}, {%4,%5,%6,%7}, {%8,%9}, {%0,%1,%2,%3};" \
                 : "+f"((d)[0]), "+f"((d)[1]), "+f"((d)[2]), "+f"((d)[3]) \
                 : "r"((a)[0]), "r"((a)[1]), "r"((a)[2]), "r"((a)[3]), \
                   "r"((b)[0]), "r"((b)[1]))

__device__ __forceinline__ uint32_t packh2(float a, float b) {
    __half2 t;
    t.x = __float2half_rn(a);
    t.y = __float2half_rn(b);
    return *(uint32_t*)&t;
}

// ============================================================================
// Fused weight transpose + fp16 cast for all 7 weights (grid.z selects).
// ============================================================================
__global__ void __launch_bounds__(256)
wsplit_all(const float* __restrict__ We, const float* __restrict__ Wq,
           const float* __restrict__ Wk, const float* __restrict__ Wv,
           const float* __restrict__ W0, const float* __restrict__ W1,
           const float* __restrict__ W2, __half* __restrict__ ThB)
{
    const int z = blockIdx.z;
    const int K = (z == 0) ? DIN : DMODEL;
    if ((int)blockIdx.y * 32 >= K) return;
    const float* W = (z == 0) ? We : (z == 1) ? Wq : (z == 2) ? Wk :
                     (z == 3) ? Wv : (z == 4) ? W0 : (z == 5) ? W1 : W2;
    const size_t off = (z == 0) ? 0 : (size_t)WSZ_E + (size_t)(z - 1) * WSZ;
    __half* Th = ThB + off;

    __shared__ float t[32][33];
    const int tx = threadIdx.x, ty = threadIdx.y;
    const int n = blockIdx.x * 32 + tx;
#pragma unroll
    for (int i = 0; i < 4; i++) {
        const int k = blockIdx.y * 32 + ty + i * 8;
        t[ty + i * 8][tx] = W[(size_t)k * DMODEL + n];
    }
    __syncthreads();
    const int k2 = blockIdx.y * 32 + tx;
#pragma unroll
    for (int i = 0; i < 4; i++) {
        const int n2 = blockIdx.x * 32 + ty + i * 8;
        Th[(size_t)n2 * K + k2] = __float2half_rn(t[tx][ty + i * 8]);
    }
}

__global__ void __launch_bounds__(256)
xsplit(const float* __restrict__ X, __half* __restrict__ H, __half* __restrict__ L)
{
    const int i = blockIdx.x * 256 + threadIdx.x;
    const float2 v = ((const float2*)X)[i];
    const __half hx = __float2half_rn(v.x);
    const __half hy = __float2half_rn(v.y);
    __half2 hp, lp;
    hp.x = hx; hp.y = hy;
    lp.x = __float2half_rn(v.x - __half2float(hx));
    lp.y = __float2half_rn(v.y - __half2float(hy));
    ((__half2*)H)[i] = hp;
    ((__half2*)L)[i] = lp;
}

// ============================================================================
// GEMM: CTA tile 128x256, BK=64 (row stride 144B, conflict-free ldmatrix),
// 256 threads = 8 warps (2m x 4n), warp tile 64x64.
// fp16 2-pass: C = Ah*Wh + Al*Wh.  Double-buffered cp.async.
// ============================================================================
#define GA_TILE 18432
#define GB_TILE 36864
#define GBUF    (2*GA_TILE + GB_TILE)     // 73728
#define GEMM_SMEM (2*GBUF)                // 147456

#define GEMM_MAINLOOP(K_)                                                       \
    float acc[4][8][4];                                                         \
    _Pragma("unroll")                                                           \
    for (int mf = 0; mf < 4; mf++)                                              \
        _Pragma("unroll")                                                       \
        for (int nf = 0; nf < 8; nf++)                                          \
            _Pragma("unroll")                                                   \
            for (int j = 0; j < 4; j++) acc[mf][nf][j] = 0.f;                   \
    const int NIT = (K_) >> 6;                                                  \
    auto issue = [&](int it) {                                                  \
        const int k0 = it << 6;                                                 \
        const uint32_t db = sb + (uint32_t)(it & 1) * GBUF;                     \
        _Pragma("unroll")                                                       \
        for (int t = 0; t < 2; t++) {                                           \
            _Pragma("unroll")                                                   \
            for (int s = 0; s < 4; s++) {                                       \
                const int id = tid + s * 256;                                   \
                const int row = id >> 3, c = id & 7;                            \
                const __half* g = srcs[t] + (size_t)row * (K_) + k0 + c * 8;    \
                CP_ASYNC16(db + (uint32_t)t * GA_TILE                           \
                           + (uint32_t)(row * 144 + c * 16), g);                \
            }                                                                   \
        }                                                                       \
        _Pragma("unroll")                                                       \
        for (int s = 0; s < 8; s++) {                                           \
            const int id = tid + s * 256;                                       \
            const int row = id >> 3, c = id & 7;                                \
            const __half* g = srcs[2] + (size_t)row * (K_) + k0 + c * 8;        \
            CP_ASYNC16(db + 2u * GA_TILE                                        \
                       + (uint32_t)(row * 144 + c * 16), g);                    \
        }                                                                       \
        CP_COMMIT();                                                            \
    };                                                                          \
    issue(0);                                                                   \
    const int a_r  = lane & 15;                                                 \
    const int a_kh = lane >> 4;                                                 \
    const int b_nl = (lane & 7) + ((lane >> 4) << 3);                           \
    const int b_kh = (lane >> 3) & 1;                                           \
    for (int it = 0; it < NIT; it++) {                                          \
        if (it + 1 < NIT) { issue(it + 1); CP_WAIT1(); }                        \
        else              { CP_WAIT0(); }                                       \
        __syncthreads();                                                        \
        const uint32_t db = sb + (uint32_t)(it & 1) * GBUF;                     \
        _Pragma("unroll")                                                       \
        for (int ks = 0; ks < 4; ks++) {                                        \
            uint32_t ah[4][4], al[4][4], bh[8][2];                              \
            _Pragma("unroll")                                                   \
            for (int mf = 0; mf < 4; mf++) {                                    \
                const uint32_t aoff = (uint32_t)((wm * 64 + mf * 16 + a_r) * 144 \
                                               + (ks * 16 + a_kh * 8) * 2);     \
                LDSM4(ah[mf][0], ah[mf][1], ah[mf][2], ah[mf][3], db + aoff);   \
                LDSM4(al[mf][0], al[mf][1], al[mf][2], al[mf][3],               \
                      db + GA_TILE + aoff);                                     \
            }                                                                   \
            _Pragma("unroll")                                                   \
            for (int nf2 = 0; nf2 < 4; nf2++) {                                 \
                const uint32_t boff = (uint32_t)((wn * 64 + nf2 * 16 + b_nl) * 144 \
                                               + (ks * 16 + b_kh * 8) * 2);     \
                LDSM4(bh[2*nf2][0], bh[2*nf2][1], bh[2*nf2+1][0], bh[2*nf2+1][1], \
                      db + 2u * GA_TILE + boff);                                \
            }                                                                   \
            _Pragma("unroll")                                                   \
            for (int mf = 0; mf < 4; mf++)                                      \
                _Pragma("unroll")                                               \
                for (int nf = 0; nf < 8; nf++)                                  \
                    MMA16816(acc[mf][nf], ah[mf], bh[nf]);                      \
            _Pragma("unroll")                                                   \
            for (int mf = 0; mf < 4; mf++)                                      \
                _Pragma("unroll")                                               \
                for (int nf = 0; nf < 8; nf++)                                  \
                    MMA16816(acc[mf][nf], al[mf], bh[nf]);                      \
        }                                                                       \
        __syncthreads();                                                        \
    }

// ---- generic GEMM: hi/lo residual, fp32 and/or fp16 hi/lo out, bias/relu ----
__global__ void __launch_bounds__(256)
gemm_mma(const __half* __restrict__ Ah, const __half* __restrict__ Al,
         const __half* __restrict__ Bh,
         const float* __restrict__ bias,
         const __half* __restrict__ resh, const __half* __restrict__ resl,
         float* __restrict__ Cf, __half* __restrict__ Ch,
         __half* __restrict__ Cl, int K, int relu)
{
    extern __shared__ char smem[];
    const uint32_t sb = smem_u32(smem);
    const int tid  = threadIdx.x;
    const int wid  = tid >> 5;
    const int lane = tid & 31;
    const int wm = wid >> 2;
    const int wn = wid & 3;
    const int m0 = blockIdx.y * 128;
    const int n0 = blockIdx.x * 256;

    const __half* srcs[3] = {
        Ah + (size_t)m0 * K, Al + (size_t)m0 * K, Bh + (size_t)n0 * K };

    GEMM_MAINLOOP(K)

    const int g  = lane >> 2;
    const int i2 = (lane & 3) << 1;
#pragma unroll
    for (int mf = 0; mf < 4; mf++) {
        const int rowa = m0 + wm * 64 + mf * 16 + g;
        const int rowb = rowa + 8;
#pragma unroll
        for (int nf = 0; nf < 8; nf++) {
            const int col = n0 + wn * 64 + nf * 8 + i2;
            const float2 b2 = *(const float2*)&bias[col];
            float v0 = acc[mf][nf][0] + b2.x;
            float v1 = acc[mf][nf][1] + b2.y;
            float v2 = acc[mf][nf][2] + b2.x;
            float v3 = acc[mf][nf][3] + b2.y;
            if (relu) {
                v0 = fmaxf(v0, 0.f); v1 = fmaxf(v1, 0.f);
                v2 = fmaxf(v2, 0.f); v3 = fmaxf(v3, 0.f);
            }
            if (resh) {
                const __half2 ha = *(const __half2*)&resh[(size_t)rowa * DMODEL + col];
                const __half2 la = *(const __half2*)&resl[(size_t)rowa * DMODEL + col];
                const __half2 hb = *(const __half2*)&resh[(size_t)rowb * DMODEL + col];
                const __half2 lb = *(const __half2*)&resl[(size_t)rowb * DMODEL + col];
                v0 += __half2float(ha.x) + __half2float(la.x);
                v1 += __half2float(ha.y) + __half2float(la.y);
                v2 += __half2float(hb.x) + __half2float(lb.x);
                v3 += __half2float(hb.y) + __half2float(lb.y);
            }
            if (Cf) {
                *(float2*)&Cf[(size_t)rowa * DMODEL + col] = make_float2(v0, v1);
                *(float2*)&Cf[(size_t)rowb * DMODEL + col] = make_float2(v2, v3);
            }
            if (Ch) {
                uint32_t hp = packh2(v0, v1);
                const __half2 h2a = *(const __half2*)&hp;
                uint32_t lp = packh2(v0 - __half2float(h2a.x), v1 - __half2float(h2a.y));
                *(uint32_t*)&Ch[(size_t)rowa * DMODEL + col] = hp;
                *(uint32_t*)&Cl[(size_t)rowa * DMODEL + col] = lp;
                hp = packh2(v2, v3);
                const __half2 h2b = *(const __half2*)&hp;
                lp = packh2(v2 - __half2float(h2b.x), v3 - __half2float(h2b.y));
                *(uint32_t*)&Ch[(size_t)rowb * DMODEL + col] = hp;
                *(uint32_t*)&Cl[(size_t)rowb * DMODEL + col] = lp;
            }
        }
    }
}

// ---- fused QKV GEMM: N=3072 (Wq|Wk|Wv contiguous). q gets hi+lo; k,v hi only.
__global__ void __launch_bounds__(256)
gemm_qkv(const __half* __restrict__ Ah, const __half* __restrict__ Al,
         const __half* __restrict__ Bh,
         const float* __restrict__ bq, const float* __restrict__ bk,
         const float* __restrict__ bv,
         __half* __restrict__ qh, __half* __restrict__ ql,
         __half* __restrict__ kh, __half* __restrict__ vh)
{
    extern __shared__ char smem[];
    const uint32_t sb = smem_u32(smem);
    const int tid  = threadIdx.x;
    const int wid  = tid >> 5;
    const int lane = tid & 31;
    const int wm = wid >> 2;
    const int wn = wid & 3;
    const int m0 = blockIdx.y * 128;
    const int n0 = blockIdx.x * 256;      // global n in [0, 3072)
    const int K = DMODEL;

    const __half* srcs[3] = {
        Ah + (size_t)m0 * K, Al + (size_t)m0 * K, Bh + (size_t)n0 * K };

    GEMM_MAINLOOP(K)

    const int selq = n0 >> 10;
    const int nc0  = n0 & 1023;
    const float* bias = (selq == 0) ? bq : (selq == 1) ? bk : bv;
    __half* Oh = (selq == 0) ? qh : (selq == 1) ? kh : vh;
    __half* Ol = (selq == 0) ? ql : nullptr;

    const int g  = lane >> 2;
    const int i2 = (lane & 3) << 1;
#pragma unroll
    for (int mf = 0; mf < 4; mf++) {
        const int rowa = m0 + wm * 64 + mf * 16 + g;
        const int rowb = rowa + 8;
#pragma unroll
        for (int nf = 0; nf < 8; nf++) {
            const int col = nc0 + wn * 64 + nf * 8 + i2;
            const float2 b2 = *(const float2*)&bias[col];
            const float v0 = acc[mf][nf][0] + b2.x;
            const float v1 = acc[mf][nf][1] + b2.y;
            const float v2 = acc[mf][nf][2] + b2.x;
            const float v3 = acc[mf][nf][3] + b2.y;
            const uint32_t hpa = packh2(v0, v1);
            const uint32_t hpb = packh2(v2, v3);
            *(uint32_t*)&Oh[(size_t)rowa * DMODEL + col] = hpa;
            *(uint32_t*)&Oh[(size_t)rowb * DMODEL + col] = hpb;
            if (Ol) {
                const __half2 h2a = *(const __half2*)&hpa;
                const __half2 h2b = *(const __half2*)&hpb;
                *(uint32_t*)&Ol[(size_t)rowa * DMODEL + col] =
                    packh2(v0 - __half2float(h2a.x), v1 - __half2float(h2a.y));
                *(uint32_t*)&Ol[(size_t)rowb * DMODEL + col] =
                    packh2(v2 - __half2float(h2b.x), v3 - __half2float(h2b.y));
            }
        }
    }
}

// ============================================================================
// Tensor-core flash attention, fp16.
// Scores: QhKh + QlKh (2-pass, fp32-grade logits). PV: PhVh single pass
// (P rounding ~2^-12 relative on O — within budget).
// ============================================================================
#define AT_STR    144
#define AT_QTILE  (128*AT_STR)
#define AT_KVT    (64*AT_STR)
#define AT_BUF    (2*AT_KVT)
#define AT_Q      (2*AT_QTILE)
#define AT_SMEM   (AT_Q + 2*AT_BUF)     // 73728

__global__ void __launch_bounds__(256, 1)
attn_mma(const __half* __restrict__ Qh, const __half* __restrict__ Ql,
         const __half* __restrict__ Kh, const __half* __restrict__ Vh,
         __half* __restrict__ Ch, __half* __restrict__ Cl)
{
    extern __shared__ char smem[];
    const uint32_t sb = smem_u32(smem);
    const int tid  = threadIdx.x;
    const int wid  = tid >> 5;
    const int lane = tid & 31;
    const int q0   = blockIdx.x * 128;
    const int bh   = blockIdx.y;
    const int b    = bh >> 4;
    const int h    = bh & (NHEAD - 1);
    const size_t base = (size_t)b * SEQ * DMODEL + (size_t)h * 64;
    const float scale = 0.125f;

    const __half* kvs[2] = { Kh + base, Vh + base };

    auto issue = [&](int it) {
        const int kv0 = it << 6;
        const uint32_t db = sb + AT_Q + (uint32_t)(it & 1) * AT_BUF;
#pragma unroll
        for (int t = 0; t < 2; t++) {
#pragma unroll
            for (int s = 0; s < 2; s++) {
                const int id = tid + s * 256;
                const int row = id >> 3, c16 = id & 7;
                const __half* g = kvs[t] + (size_t)(kv0 + row) * DMODEL + c16 * 8;
                const uint32_t d = db + (uint32_t)t * AT_KVT + (uint32_t)(row * AT_STR + c16 * 16);
                CP_ASYNC16(d, g);
            }
        }
        CP_COMMIT();
    };

    issue(0);

#pragma unroll
    for (int s = 0; s < 4; s++) {
        const int id = tid + s * 256;
        const int row = id >> 3, c16 = id & 7;
        const size_t g = base + (size_t)(q0 + row) * DMODEL + c16 * 8;
        const uint32_t d = (uint32_t)(row * AT_STR + c16 * 16);
        *(uint4*)(smem + d)            = *(const uint4*)(Qh + g);
        *(uint4*)(smem + AT_QTILE + d) = *(const uint4*)(Ql + g);
    }
    __syncthreads();

    const int tq  = lane & 7;
    const int sel = lane >> 3;
    const int wq0 = wid * 16;
    uint32_t qfh[4][4], qfl[4][4];
    {
        const int arow = wq0 + tq + (sel & 1) * 8;
#pragma unroll
        for (int ks = 0; ks < 4; ks++) {
            const uint32_t a = sb + (uint32_t)(arow * AT_STR + (ks * 16 + (sel >> 1) * 8) * 2);
            LDSM4(qfh[ks][0], qfh[ks][1], qfh[ks][2], qfh[ks][3], a);
            LDSM4(qfl[ks][0], qfl[ks][1], qfl[ks][2], qfl[ks][3], a + AT_QTILE);
        }
    }

    float oacc[8][4];
#pragma unroll
    for (int nf = 0; nf < 8; nf++)
#pragma unroll
        for (int j = 0; j < 4; j++) oacc[nf][j] = 0.f;
    float m0 = -1e30f, m1 = -1e30f, l0 = 0.f, l1 = 0.f;

    const int NIT = SEQ / 64;
    for (int it = 0; it < NIT; it++) {
        if (it + 1 < NIT) { issue(it + 1); CP_WAIT1(); }
        else              { CP_WAIT0(); }
        __syncthreads();
        const uint32_t db = sb + AT_Q + (uint32_t)(it & 1) * AT_BUF;

        float sacc[8][4];
#pragma unroll
        for (int nf = 0; nf < 8; nf++)
#pragma unroll
            for (int j = 0; j < 4; j++) sacc[nf][j] = 0.f;

        // scores: QhKh + QlKh
#pragma unroll
        for (int ks = 0; ks < 4; ks++) {
            uint32_t bf[8][2];
#pragma unroll
            for (int p = 0; p < 4; p++) {
                const uint32_t a = db + (uint32_t)(((p * 16) + tq + (sel >> 1) * 8) * AT_STR
                                                 + (ks * 16 + (sel & 1) * 8) * 2);
                LDSM4(bf[2*p][0], bf[2*p][1], bf[2*p+1][0], bf[2*p+1][1], a);
            }
#pragma unroll
            for (int nf = 0; nf < 8; nf++) MMA16816(sacc[nf], qfh[ks], bf[nf]);
#pragma unroll
            for (int nf = 0; nf < 8; nf++) MMA16816(sacc[nf], qfl[ks], bf[nf]);
        }

#pragma unroll
        for (int nf = 0; nf < 8; nf++)
#pragma unroll
            for (int j = 0; j < 4; j++) sacc[nf][j] *= scale;

        float mx0 = -1e30f, mx1 = -1e30f;
#pragma unroll
        for (int nf = 0; nf < 8; nf++) {
            mx0 = fmaxf(mx0, fmaxf(sacc[nf][0], sacc[nf][1]));
            mx1 = fmaxf(mx1, fmaxf(sacc[nf][2], sacc[nf][3]));
        }
        mx0 = fmaxf(mx0, __shfl_xor_sync(0xffffffffu, mx0, 1));
        mx0 = fmaxf(mx0, __shfl_xor_sync(0xffffffffu, mx0, 2));
        mx1 = fmaxf(mx1, __shfl_xor_sync(0xffffffffu, mx1, 1));
        mx1 = fmaxf(mx1, __shfl_xor_sync(0xffffffffu, mx1, 2));

        const float mn0 = fmaxf(m0, mx0);
        const float mn1 = fmaxf(m1, mx1);
        const float al0 = __expf(m0 - mn0);
        const float al1 = __expf(m1 - mn1);
        m0 = mn0; m1 = mn1;

        uint32_t ph[4][4];
        float sum0 = 0.f, sum1 = 0.f;
#pragma unroll
        for (int nf = 0; nf < 8; nf++) {
            const float p0 = __expf(sacc[nf][0] - m0);
            const float p1 = __expf(sacc[nf][1] - m0);
            const float p2 = __expf(sacc[nf][2] - m1);
            const float p3 = __expf(sacc[nf][3] - m1);
            sum0 += p0 + p1;
            sum1 += p2 + p3;
            const int kf = nf >> 1, hf = (nf & 1) * 2;
            ph[kf][hf]     = packh2(p0, p1);
            ph[kf][hf + 1] = packh2(p2, p3);
        }
        sum0 += __shfl_xor_sync(0xffffffffu, sum0, 1);
        sum0 += __shfl_xor_sync(0xffffffffu, sum0, 2);
        sum1 += __shfl_xor_sync(0xffffffffu, sum1, 1);
        sum1 += __shfl_xor_sync(0xffffffffu, sum1, 2);
        l0 = l0 * al0 + sum0;
        l1 = l1 * al1 + sum1;
#pragma unroll
        for (int nf = 0; nf < 8; nf++) {
            oacc[nf][0] *= al0; oacc[nf][1] *= al0;
            oacc[nf][2] *= al1; oacc[nf][3] *= al1;
        }

        // PV: PhVh single pass
#pragma unroll
        for (int kst = 0; kst < 4; kst++) {
            uint32_t vf[8][2];
#pragma unroll
            for (int p = 0; p < 4; p++) {
                const uint32_t a = db + AT_KVT
                    + (uint32_t)((kst * 16 + tq + (sel & 1) * 8) * AT_STR
                               + (p * 16 + (sel >> 1) * 8) * 2);
                LDSM4T(vf[2*p][0], vf[2*p][1], vf[2*p+1][0], vf[2*p+1][1], a);
            }
#pragma unroll
            for (int nf = 0; nf < 8; nf++) MMA16816(oacc[nf], ph[kst], vf[nf]);
        }
        __syncthreads();
    }

    const float inv0 = 1.f / l0;
    const float inv1 = 1.f / l1;
    const int g  = lane >> 2;
    const int i2 = (lane & 3) << 1;
    const int row0 = q0 + wq0 + g;
    const int row1 = row0 + 8;
#pragma unroll
    for (int nf = 0; nf < 8; nf++) {
        const int coff = nf * 8 + i2;
        const float v0 = oacc[nf][0] * inv0;
        const float v1 = oacc[nf][1] * inv0;
        const float v2 = oacc[nf][2] * inv1;
        const float v3 = oacc[nf][3] * inv1;
        uint32_t hp = packh2(v0, v1);
        __half2 h2 = *(const __half2*)&hp;
        *(uint32_t*)&Ch[base + (size_t)row0 * DMODEL + coff] = hp;
        *(uint32_t*)&Cl[base + (size_t)row0 * DMODEL + coff] =
            packh2(v0 - __half2float(h2.x), v1 - __half2float(h2.y));
        hp = packh2(v2, v3);
        h2 = *(const __half2*)&hp;
        *(uint32_t*)&Ch[base + (size_t)row1 * DMODEL + coff] = hp;
        *(uint32_t*)&Cl[base + (size_t)row1 * DMODEL + coff] =
            packh2(v2 - __half2float(h2.x), v3 - __half2float(h2.y));
    }
}

// ============================================================================
// kernel_launch
// ============================================================================
extern "C" void kernel_launch(void* const* d_in, const int* in_sizes, int n_in,
                              void* d_out, int out_size)
{
    (void)in_sizes; (void)n_in; (void)out_size;

    const float* x  = (const float*)d_in[0];
    const float* We = (const float*)d_in[1];
    const float* be = (const float*)d_in[2];
    const float* Wq = (const float*)d_in[3];
    const float* bq = (const float*)d_in[4];
    const float* Wk = (const float*)d_in[5];
    const float* bk = (const float*)d_in[6];
    const float* Wv = (const float*)d_in[7];
    const float* bv = (const float*)d_in[8];
    const float* W0 = (const float*)d_in[9];
    const float* b0 = (const float*)d_in[10];
    const float* W1 = (const float*)d_in[11];
    const float* b1 = (const float*)d_in[12];
    const float* W2 = (const float*)d_in[13];
    const float* b2 = (const float*)d_in[14];
    float* out = (float*)d_out;

    __half *xh, *xl, *eh, *el, *qh, *ql, *kh, *vh;
    __half *ch, *cl, *mh, *ml, *hh, *hl, *Wh;
    cudaGetSymbolAddress((void**)&xh,  g_xh);
    cudaGetSymbolAddress((void**)&xl,  g_xl);
    cudaGetSymbolAddress((void**)&eh,  g_eh);
    cudaGetSymbolAddress((void**)&el,  g_el);
    cudaGetSymbolAddress((void**)&qh,  g_qh);
    cudaGetSymbolAddress((void**)&ql,  g_ql);
    cudaGetSymbolAddress((void**)&kh,  g_kh);
    cudaGetSymbolAddress((void**)&vh,  g_vh);
    cudaGetSymbolAddress((void**)&ch,  g_ch);
    cudaGetSymbolAddress((void**)&cl,  g_cl);
    cudaGetSymbolAddress((void**)&mh,  g_mh);
    cudaGetSymbolAddress((void**)&ml,  g_ml);
    cudaGetSymbolAddress((void**)&hh,  g_hh);
    cudaGetSymbolAddress((void**)&hl,  g_hl);
    cudaGetSymbolAddress((void**)&Wh,  g_Wh);

    cudaFuncSetAttribute(gemm_mma, cudaFuncAttributeMaxDynamicSharedMemorySize, GEMM_SMEM);
    cudaFuncSetAttribute(gemm_qkv, cudaFuncAttributeMaxDynamicSharedMemorySize, GEMM_SMEM);
    cudaFuncSetAttribute(attn_mma, cudaFuncAttributeMaxDynamicSharedMemorySize, AT_SMEM);

    // all weight transposes+casts in one launch; x split
    wsplit_all<<<dim3(32, 32, 7), dim3(32, 8)>>>(We, Wq, Wk, Wv, W0, W1, W2, Wh);
    xsplit<<<MROWS * DIN / 512, 256>>>(x, xh, xl);

    __half* Wqh = Wh + WSZ_E;
    __half* W0h = Wqh + 3*WSZ;
    __half* W1h = W0h + WSZ;
    __half* W2h = W1h + WSZ;

    const dim3 gg(4, 32);   // (N/256, M/128)
    // e = x @ We + be  (hi/lo only)
    gemm_mma<<<gg, 256, GEMM_SMEM>>>(xh, xl, Wh, be, nullptr, nullptr,
                                     nullptr, eh, el, DIN, 0);
    // q,k,v fused (q: hi/lo; k,v: hi)
    gemm_qkv<<<dim3(12, 32), 256, GEMM_SMEM>>>(eh, el, Wqh, bq, bk, bv, qh, ql, kh, vh);
    // attention -> ctx (fp16 hi/lo)
    attn_mma<<<dim3(SEQ / 128, 32), 256, AT_SMEM>>>(qh, ql, kh, vh, ch, cl);
    // mha = (eh+el) + ctx @ W0 + b0  (hi/lo only)
    gemm_mma<<<gg, 256, GEMM_SMEM>>>(ch, cl, W0h, b0, eh, el,
                                     nullptr, mh, ml, DMODEL, 0);
    // h1 = relu(mha @ W1 + b1)  (hi/lo only)
    gemm_mma<<<gg, 256, GEMM_SMEM>>>(mh, ml, W1h, b1, nullptr, nullptr,
                                     nullptr, hh, hl, DMODEL, 1);
    // out = (mh+ml) + h1 @ W2 + b2  (fp32)
    gemm_mma<<<gg, 256, GEMM_SMEM>>>(hh, hl, W2h, b2, mh, ml,
                                     out, nullptr, nullptr, DMODEL, 0);
}

// round 17
// speedup vs baseline: 2.0946x; 1.2937x over previous
#include <cuda_runtime.h>
#include <cuda_fp16.h>
#include <cstdint>

#define MROWS  4096
#define DMODEL 1024
#define DIN    512
#define NHEAD  16
#define SEQ    2048

// ---------------- scratch (allocation-free) ----------------
__device__ __align__(128) __half g_xh[MROWS*DIN];
__device__ __align__(128) __half g_eh[MROWS*DMODEL], g_el[MROWS*DMODEL];
__device__ __align__(128) __half g_qh[MROWS*DMODEL], g_ql[MROWS*DMODEL];
__device__ __align__(128) __half g_kh[MROWS*DMODEL];
__device__ __align__(128) __half g_vh[MROWS*DMODEL];
__device__ __align__(128) __half g_ch[MROWS*DMODEL];
__device__ __align__(128) __half g_mh[MROWS*DMODEL], g_ml[MROWS*DMODEL];
__device__ __align__(128) __half g_hh[MROWS*DMODEL];
#define WSZ_E (DMODEL*DIN)
#define WSZ   (DMODEL*DMODEL)
__device__ __align__(128) __half g_Wh[WSZ_E + 6*WSZ];

// ---------------- helpers ----------------
__device__ __forceinline__ uint32_t smem_u32(const void* p) {
    uint32_t a;
    asm("{ .reg .u64 t; cvta.to.shared.u64 t, %1; cvt.u32.u64 %0, t; }" : "=r"(a) : "l"(p));
    return a;
}

#define CP_ASYNC16(dst, src) \
    asm volatile("cp.async.cg.shared.global [%0], [%1], 16;" :: "r"(dst), "l"(src) : "memory")
#define CP_COMMIT()  asm volatile("cp.async.commit_group;" ::: "memory")
#define CP_WAIT1()   asm volatile("cp.async.wait_group 1;" ::: "memory")
#define CP_WAIT0()   asm volatile("cp.async.wait_group 0;" ::: "memory")

#define LDSM4(r0, r1, r2, r3, a) \
    asm volatile("ldmatrix.sync.aligned.m8n8.x4.shared.b16 {%0,%1,%2,%3}, [%4];" \
                 : "=r"(r0), "=r"(r1), "=r"(r2), "=r"(r3) : "r"(a))
#define LDSM4T(r0, r1, r2, r3, a) \
    asm volatile("ldmatrix.sync.aligned.m8n8.x4.trans.shared.b16 {%0,%1,%2,%3}, [%4];" \
                 : "=r"(r0), "=r"(r1), "=r"(r2), "=r"(r3) : "r"(a))

#define MMA16816(d, a, b) \
    asm volatile("mma.sync.aligned.m16n8k16.row.col.f32.f16.f16.f32 " \
                 "{%0,%1,%2,%3}, {%4,%5,%6,%7}, {%8,%9}, {%0,%1,%2,%3};" \
                 : "+f"((d)[0]), "+f"((d)[1]), "+f"((d)[2]), "+f"((d)[3]) \
                 : "r"((a)[0]), "r"((a)[1]), "r"((a)[2]), "r"((a)[3]), \
                   "r"((b)[0]), "r"((b)[1]))

__device__ __forceinline__ uint32_t packh2(float a, float b) {
    __half2 t;
    t.x = __float2half_rn(a);
    t.y = __float2half_rn(b);
    return *(uint32_t*)&t;
}

// ============================================================================
// Fused weight transpose + fp16 cast for all 7 weights (grid.z selects).
// ============================================================================
__global__ void __launch_bounds__(256)
wsplit_all(const float* __restrict__ We, const float* __restrict__ Wq,
           const float* __restrict__ Wk, const float* __restrict__ Wv,
           const float* __restrict__ W0, const float* __restrict__ W1,
           const float* __restrict__ W2, __half* __restrict__ ThB)
{
    const int z = blockIdx.z;
    const int K = (z == 0) ? DIN : DMODEL;
    if ((int)blockIdx.y * 32 >= K) return;
    const float* W = (z == 0) ? We : (z == 1) ? Wq : (z == 2) ? Wk :
                     (z == 3) ? Wv : (z == 4) ? W0 : (z == 5) ? W1 : W2;
    const size_t off = (z == 0) ? 0 : (size_t)WSZ_E + (size_t)(z - 1) * WSZ;
    __half* Th = ThB + off;

    __shared__ float t[32][33];
    const int tx = threadIdx.x, ty = threadIdx.y;
    const int n = blockIdx.x * 32 + tx;
#pragma unroll
    for (int i = 0; i < 4; i++) {
        const int k = blockIdx.y * 32 + ty + i * 8;
        t[ty + i * 8][tx] = W[(size_t)k * DMODEL + n];
    }
    __syncthreads();
    const int k2 = blockIdx.y * 32 + tx;
#pragma unroll
    for (int i = 0; i < 4; i++) {
        const int n2 = blockIdx.x * 32 + ty + i * 8;
        Th[(size_t)n2 * K + k2] = __float2half_rn(t[tx][ty + i * 8]);
    }
}

// x -> fp16 cast (hi only; lo term dropped by the 1-pass GEMM)
__global__ void __launch_bounds__(256)
xcast(const float* __restrict__ X, __half* __restrict__ H)
{
    const int i = blockIdx.x * 256 + threadIdx.x;
    const float2 v = ((const float2*)X)[i];
    __half2 hp;
    hp.x = __float2half_rn(v.x);
    hp.y = __float2half_rn(v.y);
    ((__half2*)H)[i] = hp;
}

// ============================================================================
// GEMM: CTA tile 128x256, BK=64 (row stride 144B, conflict-free ldmatrix),
// 256 threads = 8 warps (2m x 4n), warp tile 64x64.
// fp16 1-pass: C = Ah*Wh.  Double-buffered cp.async.
// Per buffer: Ah 128x144B (18432) + Bh 256x144B (36864) = 55296; x2.
// ============================================================================
#define GA_TILE 18432
#define GB_TILE 36864
#define GBUF    (GA_TILE + GB_TILE)       // 55296
#define GEMM_SMEM (2*GBUF)                // 110592

#define GEMM_MAINLOOP(K_)                                                       \
    float acc[4][8][4];                                                         \
    _Pragma("unroll")                                                           \
    for (int mf = 0; mf < 4; mf++)                                              \
        _Pragma("unroll")                                                       \
        for (int nf = 0; nf < 8; nf++)                                          \
            _Pragma("unroll")                                                   \
            for (int j = 0; j < 4; j++) acc[mf][nf][j] = 0.f;                   \
    const int NIT = (K_) >> 6;                                                  \
    auto issue = [&](int it) {                                                  \
        const int k0 = it << 6;                                                 \
        const uint32_t db = sb + (uint32_t)(it & 1) * GBUF;                     \
        _Pragma("unroll")                                                       \
        for (int s = 0; s < 4; s++) {                                           \
            const int id = tid + s * 256;                                       \
            const int row = id >> 3, c = id & 7;                                \
            const __half* g = srcs[0] + (size_t)row * (K_) + k0 + c * 8;        \
            CP_ASYNC16(db + (uint32_t)(row * 144 + c * 16), g);                 \
        }                                                                       \
        _Pragma("unroll")                                                       \
        for (int s = 0; s < 8; s++) {                                           \
            const int id = tid + s * 256;                                       \
            const int row = id >> 3, c = id & 7;                                \
            const __half* g = srcs[1] + (size_t)row * (K_) + k0 + c * 8;        \
            CP_ASYNC16(db + (uint32_t)GA_TILE                                   \
                       + (uint32_t)(row * 144 + c * 16), g);                    \
        }                                                                       \
        CP_COMMIT();                                                            \
    };                                                                          \
    issue(0);                                                                   \
    const int a_r  = lane & 15;                                                 \
    const int a_kh = lane >> 4;                                                 \
    const int b_nl = (lane & 7) + ((lane >> 4) << 3);                           \
    const int b_kh = (lane >> 3) & 1;                                           \
    for (int it = 0; it < NIT; it++) {                                          \
        if (it + 1 < NIT) { issue(it + 1); CP_WAIT1(); }                        \
        else              { CP_WAIT0(); }                                       \
        __syncthreads();                                                        \
        const uint32_t db = sb + (uint32_t)(it & 1) * GBUF;                     \
        _Pragma("unroll")                                                       \
        for (int ks = 0; ks < 4; ks++) {                                        \
            uint32_t ah[4][4], bh[8][2];                                        \
            _Pragma("unroll")                                                   \
            for (int mf = 0; mf < 4; mf++) {                                    \
                const uint32_t aoff = (uint32_t)((wm * 64 + mf * 16 + a_r) * 144 \
                                               + (ks * 16 + a_kh * 8) * 2);     \
                LDSM4(ah[mf][0], ah[mf][1], ah[mf][2], ah[mf][3], db + aoff);   \
            }                                                                   \
            _Pragma("unroll")                                                   \
            for (int nf2 = 0; nf2 < 4; nf2++) {                                 \
                const uint32_t boff = (uint32_t)((wn * 64 + nf2 * 16 + b_nl) * 144 \
                                               + (ks * 16 + b_kh * 8) * 2);     \
                LDSM4(bh[2*nf2][0], bh[2*nf2][1], bh[2*nf2+1][0], bh[2*nf2+1][1], \
                      db + (uint32_t)GA_TILE + boff);                           \
            }                                                                   \
            _Pragma("unroll")                                                   \
            for (int mf = 0; mf < 4; mf++)                                      \
                _Pragma("unroll")                                               \
                for (int nf = 0; nf < 8; nf++)                                  \
                    MMA16816(acc[mf][nf], ah[mf], bh[nf]);                      \
        }                                                                       \
        __syncthreads();                                                        \
    }

// ---- generic GEMM: hi/lo residual, fp32 / fp16 hi (+opt lo) out, bias/relu --
__global__ void __launch_bounds__(256)
gemm_mma(const __half* __restrict__ Ah, const __half* __restrict__ Bh,
         const float* __restrict__ bias,
         const __half* __restrict__ resh, const __half* __restrict__ resl,
         float* __restrict__ Cf, __half* __restrict__ Ch,
         __half* __restrict__ Cl, int K, int relu)
{
    extern __shared__ char smem[];
    const uint32_t sb = smem_u32(smem);
    const int tid  = threadIdx.x;
    const int wid  = tid >> 5;
    const int lane = tid & 31;
    const int wm = wid >> 2;
    const int wn = wid & 3;
    const int m0 = blockIdx.y * 128;
    const int n0 = blockIdx.x * 256;

    const __half* srcs[2] = { Ah + (size_t)m0 * K, Bh + (size_t)n0 * K };

    GEMM_MAINLOOP(K)

    const int g  = lane >> 2;
    const int i2 = (lane & 3) << 1;
#pragma unroll
    for (int mf = 0; mf < 4; mf++) {
        const int rowa = m0 + wm * 64 + mf * 16 + g;
        const int rowb = rowa + 8;
#pragma unroll
        for (int nf = 0; nf < 8; nf++) {
            const int col = n0 + wn * 64 + nf * 8 + i2;
            const float2 b2 = *(const float2*)&bias[col];
            float v0 = acc[mf][nf][0] + b2.x;
            float v1 = acc[mf][nf][1] + b2.y;
            float v2 = acc[mf][nf][2] + b2.x;
            float v3 = acc[mf][nf][3] + b2.y;
            if (relu) {
                v0 = fmaxf(v0, 0.f); v1 = fmaxf(v1, 0.f);
                v2 = fmaxf(v2, 0.f); v3 = fmaxf(v3, 0.f);
            }
            if (resh) {
                const __half2 ha = *(const __half2*)&resh[(size_t)rowa * DMODEL + col];
                const __half2 la = *(const __half2*)&resl[(size_t)rowa * DMODEL + col];
                const __half2 hb = *(const __half2*)&resh[(size_t)rowb * DMODEL + col];
                const __half2 lb = *(const __half2*)&resl[(size_t)rowb * DMODEL + col];
                v0 += __half2float(ha.x) + __half2float(la.x);
                v1 += __half2float(ha.y) + __half2float(la.y);
                v2 += __half2float(hb.x) + __half2float(lb.x);
                v3 += __half2float(hb.y) + __half2float(lb.y);
            }
            if (Cf) {
                *(float2*)&Cf[(size_t)rowa * DMODEL + col] = make_float2(v0, v1);
                *(float2*)&Cf[(size_t)rowb * DMODEL + col] = make_float2(v2, v3);
            }
            if (Ch) {
                const uint32_t hpa = packh2(v0, v1);
                const uint32_t hpb = packh2(v2, v3);
                *(uint32_t*)&Ch[(size_t)rowa * DMODEL + col] = hpa;
                *(uint32_t*)&Ch[(size_t)rowb * DMODEL + col] = hpb;
                if (Cl) {
                    const __half2 h2a = *(const __half2*)&hpa;
                    const __half2 h2b = *(const __half2*)&hpb;
                    *(uint32_t*)&Cl[(size_t)rowa * DMODEL + col] =
                        packh2(v0 - __half2float(h2a.x), v1 - __half2float(h2a.y));
                    *(uint32_t*)&Cl[(size_t)rowb * DMODEL + col] =
                        packh2(v2 - __half2float(h2b.x), v3 - __half2float(h2b.y));
                }
            }
        }
    }
}

// ---- fused QKV GEMM: N=3072 (Wq|Wk|Wv contiguous). q gets hi+lo; k,v hi only.
__global__ void __launch_bounds__(256)
gemm_qkv(const __half* __restrict__ Ah, const __half* __restrict__ Bh,
         const float* __restrict__ bq, const float* __restrict__ bk,
         const float* __restrict__ bv,
         __half* __restrict__ qh, __half* __restrict__ ql,
         __half* __restrict__ kh, __half* __restrict__ vh)
{
    extern __shared__ char smem[];
    const uint32_t sb = smem_u32(smem);
    const int tid  = threadIdx.x;
    const int wid  = tid >> 5;
    const int lane = tid & 31;
    const int wm = wid >> 2;
    const int wn = wid & 3;
    const int m0 = blockIdx.y * 128;
    const int n0 = blockIdx.x * 256;      // global n in [0, 3072)
    const int K = DMODEL;

    const __half* srcs[2] = { Ah + (size_t)m0 * K, Bh + (size_t)n0 * K };

    GEMM_MAINLOOP(K)

    const int selq = n0 >> 10;
    const int nc0  = n0 & 1023;
    const float* bias = (selq == 0) ? bq : (selq == 1) ? bk : bv;
    __half* Oh = (selq == 0) ? qh : (selq == 1) ? kh : vh;
    __half* Ol = (selq == 0) ? ql : nullptr;

    const int g  = lane >> 2;
    const int i2 = (lane & 3) << 1;
#pragma unroll
    for (int mf = 0; mf < 4; mf++) {
        const int rowa = m0 + wm * 64 + mf * 16 + g;
        const int rowb = rowa + 8;
#pragma unroll
        for (int nf = 0; nf < 8; nf++) {
            const int col = nc0 + wn * 64 + nf * 8 + i2;
            const float2 b2 = *(const float2*)&bias[col];
            const float v0 = acc[mf][nf][0] + b2.x;
            const float v1 = acc[mf][nf][1] + b2.y;
            const float v2 = acc[mf][nf][2] + b2.x;
            const float v3 = acc[mf][nf][3] + b2.y;
            const uint32_t hpa = packh2(v0, v1);
            const uint32_t hpb = packh2(v2, v3);
            *(uint32_t*)&Oh[(size_t)rowa * DMODEL + col] = hpa;
            *(uint32_t*)&Oh[(size_t)rowb * DMODEL + col] = hpb;
            if (Ol) {
                const __half2 h2a = *(const __half2*)&hpa;
                const __half2 h2b = *(const __half2*)&hpb;
                *(uint32_t*)&Ol[(size_t)rowa * DMODEL + col] =
                    packh2(v0 - __half2float(h2a.x), v1 - __half2float(h2a.y));
                *(uint32_t*)&Ol[(size_t)rowb * DMODEL + col] =
                    packh2(v2 - __half2float(h2b.x), v3 - __half2float(h2b.y));
            }
        }
    }
}

// ============================================================================
// Tensor-core flash attention, fp16.
// Scores: QhKh + QlKh (2-pass). PV: PhVh single pass. ctx hi only.
// ============================================================================
#define AT_STR    144
#define AT_QTILE  (128*AT_STR)
#define AT_KVT    (64*AT_STR)
#define AT_BUF    (2*AT_KVT)
#define AT_Q      (2*AT_QTILE)
#define AT_SMEM   (AT_Q + 2*AT_BUF)     // 73728

__global__ void __launch_bounds__(256, 1)
attn_mma(const __half* __restrict__ Qh, const __half* __restrict__ Ql,
         const __half* __restrict__ Kh, const __half* __restrict__ Vh,
         __half* __restrict__ Ch)
{
    extern __shared__ char smem[];
    const uint32_t sb = smem_u32(smem);
    const int tid  = threadIdx.x;
    const int wid  = tid >> 5;
    const int lane = tid & 31;
    const int q0   = blockIdx.x * 128;
    const int bh   = blockIdx.y;
    const int b    = bh >> 4;
    const int h    = bh & (NHEAD - 1);
    const size_t base = (size_t)b * SEQ * DMODEL + (size_t)h * 64;
    const float scale = 0.125f;

    const __half* kvs[2] = { Kh + base, Vh + base };

    auto issue = [&](int it) {
        const int kv0 = it << 6;
        const uint32_t db = sb + AT_Q + (uint32_t)(it & 1) * AT_BUF;
#pragma unroll
        for (int t = 0; t < 2; t++) {
#pragma unroll
            for (int s = 0; s < 2; s++) {
                const int id = tid + s * 256;
                const int row = id >> 3, c16 = id & 7;
                const __half* g = kvs[t] + (size_t)(kv0 + row) * DMODEL + c16 * 8;
                const uint32_t d = db + (uint32_t)t * AT_KVT + (uint32_t)(row * AT_STR + c16 * 16);
                CP_ASYNC16(d, g);
            }
        }
        CP_COMMIT();
    };

    issue(0);

#pragma unroll
    for (int s = 0; s < 4; s++) {
        const int id = tid + s * 256;
        const int row = id >> 3, c16 = id & 7;
        const size_t g = base + (size_t)(q0 + row) * DMODEL + c16 * 8;
        const uint32_t d = (uint32_t)(row * AT_STR + c16 * 16);
        *(uint4*)(smem + d)            = *(const uint4*)(Qh + g);
        *(uint4*)(smem + AT_QTILE + d) = *(const uint4*)(Ql + g);
    }
    __syncthreads();

    const int tq  = lane & 7;
    const int sel = lane >> 3;
    const int wq0 = wid * 16;
    uint32_t qfh[4][4], qfl[4][4];
    {
        const int arow = wq0 + tq + (sel & 1) * 8;
#pragma unroll
        for (int ks = 0; ks < 4; ks++) {
            const uint32_t a = sb + (uint32_t)(arow * AT_STR + (ks * 16 + (sel >> 1) * 8) * 2);
            LDSM4(qfh[ks][0], qfh[ks][1], qfh[ks][2], qfh[ks][3], a);
            LDSM4(qfl[ks][0], qfl[ks][1], qfl[ks][2], qfl[ks][3], a + AT_QTILE);
        }
    }

    float oacc[8][4];
#pragma unroll
    for (int nf = 0; nf < 8; nf++)
#pragma unroll
        for (int j = 0; j < 4; j++) oacc[nf][j] = 0.f;
    float m0 = -1e30f, m1 = -1e30f, l0 = 0.f, l1 = 0.f;

    const int NIT = SEQ / 64;
    for (int it = 0; it < NIT; it++) {
        if (it + 1 < NIT) { issue(it + 1); CP_WAIT1(); }
        else              { CP_WAIT0(); }
        __syncthreads();
        const uint32_t db = sb + AT_Q + (uint32_t)(it & 1) * AT_BUF;

        float sacc[8][4];
#pragma unroll
        for (int nf = 0; nf < 8; nf++)
#pragma unroll
            for (int j = 0; j < 4; j++) sacc[nf][j] = 0.f;

        // scores: QhKh + QlKh
#pragma unroll
        for (int ks = 0; ks < 4; ks++) {
            uint32_t bf[8][2];
#pragma unroll
            for (int p = 0; p < 4; p++) {
                const uint32_t a = db + (uint32_t)(((p * 16) + tq + (sel >> 1) * 8) * AT_STR
                                                 + (ks * 16 + (sel & 1) * 8) * 2);
                LDSM4(bf[2*p][0], bf[2*p][1], bf[2*p+1][0], bf[2*p+1][1], a);
            }
#pragma unroll
            for (int nf = 0; nf < 8; nf++) MMA16816(sacc[nf], qfh[ks], bf[nf]);
#pragma unroll
            for (int nf = 0; nf < 8; nf++) MMA16816(sacc[nf], qfl[ks], bf[nf]);
        }

#pragma unroll
        for (int nf = 0; nf < 8; nf++)
#pragma unroll
            for (int j = 0; j < 4; j++) sacc[nf][j] *= scale;

        float mx0 = -1e30f, mx1 = -1e30f;
#pragma unroll
        for (int nf = 0; nf < 8; nf++) {
            mx0 = fmaxf(mx0, fmaxf(sacc[nf][0], sacc[nf][1]));
            mx1 = fmaxf(mx1, fmaxf(sacc[nf][2], sacc[nf][3]));
        }
        mx0 = fmaxf(mx0, __shfl_xor_sync(0xffffffffu, mx0, 1));
        mx0 = fmaxf(mx0, __shfl_xor_sync(0xffffffffu, mx0, 2));
        mx1 = fmaxf(mx1, __shfl_xor_sync(0xffffffffu, mx1, 1));
        mx1 = fmaxf(mx1, __shfl_xor_sync(0xffffffffu, mx1, 2));

        const float mn0 = fmaxf(m0, mx0);
        const float mn1 = fmaxf(m1, mx1);
        const float al0 = __expf(m0 - mn0);
        const float al1 = __expf(m1 - mn1);
        m0 = mn0; m1 = mn1;

        uint32_t ph[4][4];
        float sum0 = 0.f, sum1 = 0.f;
#pragma unroll
        for (int nf = 0; nf < 8; nf++) {
            const float p0 = __expf(sacc[nf][0] - m0);
            const float p1 = __expf(sacc[nf][1] - m0);
            const float p2 = __expf(sacc[nf][2] - m1);
            const float p3 = __expf(sacc[nf][3] - m1);
            sum0 += p0 + p1;
            sum1 += p2 + p3;
            const int kf = nf >> 1, hf = (nf & 1) * 2;
            ph[kf][hf]     = packh2(p0, p1);
            ph[kf][hf + 1] = packh2(p2, p3);
        }
        sum0 += __shfl_xor_sync(0xffffffffu, sum0, 1);
        sum0 += __shfl_xor_sync(0xffffffffu, sum0, 2);
        sum1 += __shfl_xor_sync(0xffffffffu, sum1, 1);
        sum1 += __shfl_xor_sync(0xffffffffu, sum1, 2);
        l0 = l0 * al0 + sum0;
        l1 = l1 * al1 + sum1;
#pragma unroll
        for (int nf = 0; nf < 8; nf++) {
            oacc[nf][0] *= al0; oacc[nf][1] *= al0;
            oacc[nf][2] *= al1; oacc[nf][3] *= al1;
        }

        // PV: PhVh single pass
#pragma unroll
        for (int kst = 0; kst < 4; kst++) {
            uint32_t vf[8][2];
#pragma unroll
            for (int p = 0; p < 4; p++) {
                const uint32_t a = db + AT_KVT
                    + (uint32_t)((kst * 16 + tq + (sel & 1) * 8) * AT_STR
                               + (p * 16 + (sel >> 1) * 8) * 2);
                LDSM4T(vf[2*p][0], vf[2*p][1], vf[2*p+1][0], vf[2*p+1][1], a);
            }
#pragma unroll
            for (int nf = 0; nf < 8; nf++) MMA16816(oacc[nf], ph[kst], vf[nf]);
        }
        __syncthreads();
    }

    const float inv0 = 1.f / l0;
    const float inv1 = 1.f / l1;
    const int g  = lane >> 2;
    const int i2 = (lane & 3) << 1;
    const int row0 = q0 + wq0 + g;
    const int row1 = row0 + 8;
#pragma unroll
    for (int nf = 0; nf < 8; nf++) {
        const int coff = nf * 8 + i2;
        *(uint32_t*)&Ch[base + (size_t)row0 * DMODEL + coff] =
            packh2(oacc[nf][0] * inv0, oacc[nf][1] * inv0);
        *(uint32_t*)&Ch[base + (size_t)row1 * DMODEL + coff] =
            packh2(oacc[nf][2] * inv1, oacc[nf][3] * inv1);
    }
}

// ============================================================================
// kernel_launch
// ============================================================================
extern "C" void kernel_launch(void* const* d_in, const int* in_sizes, int n_in,
                              void* d_out, int out_size)
{
    (void)in_sizes; (void)n_in; (void)out_size;

    const float* x  = (const float*)d_in[0];
    const float* We = (const float*)d_in[1];
    const float* be = (const float*)d_in[2];
    const float* Wq = (const float*)d_in[3];
    const float* bq = (const float*)d_in[4];
    const float* Wk = (const float*)d_in[5];
    const float* bk = (const float*)d_in[6];
    const float* Wv = (const float*)d_in[7];
    const float* bv = (const float*)d_in[8];
    const float* W0 = (const float*)d_in[9];
    const float* b0 = (const float*)d_in[10];
    const float* W1 = (const float*)d_in[11];
    const float* b1 = (const float*)d_in[12];
    const float* W2 = (const float*)d_in[13];
    const float* b2 = (const float*)d_in[14];
    float* out = (float*)d_out;

    __half *xh, *eh, *el, *qh, *ql, *kh, *vh, *ch, *mh, *ml, *hh, *Wh;
    cudaGetSymbolAddress((void**)&xh,  g_xh);
    cudaGetSymbolAddress((void**)&eh,  g_eh);
    cudaGetSymbolAddress((void**)&el,  g_el);
    cudaGetSymbolAddress((void**)&qh,  g_qh);
    cudaGetSymbolAddress((void**)&ql,  g_ql);
    cudaGetSymbolAddress((void**)&kh,  g_kh);
    cudaGetSymbolAddress((void**)&vh,  g_vh);
    cudaGetSymbolAddress((void**)&ch,  g_ch);
    cudaGetSymbolAddress((void**)&mh,  g_mh);
    cudaGetSymbolAddress((void**)&ml,  g_ml);
    cudaGetSymbolAddress((void**)&hh,  g_hh);
    cudaGetSymbolAddress((void**)&Wh,  g_Wh);

    cudaFuncSetAttribute(gemm_mma, cudaFuncAttributeMaxDynamicSharedMemorySize, GEMM_SMEM);
    cudaFuncSetAttribute(gemm_qkv, cudaFuncAttributeMaxDynamicSharedMemorySize, GEMM_SMEM);
    cudaFuncSetAttribute(attn_mma, cudaFuncAttributeMaxDynamicSharedMemorySize, AT_SMEM);

    // all weight transposes+casts in one launch; x cast
    wsplit_all<<<dim3(32, 32, 7), dim3(32, 8)>>>(We, Wq, Wk, Wv, W0, W1, W2, Wh);
    xcast<<<MROWS * DIN / 512, 256>>>(x, xh);

    __half* Wqh = Wh + WSZ_E;
    __half* W0h = Wqh + 3*WSZ;
    __half* W1h = W0h + WSZ;
    __half* W2h = W1h + WSZ;

    const dim3 gg(4, 32);   // (N/256, M/128)
    // e = x @ We + be  (hi/lo out; lo kept for the residual reconstruction)
    gemm_mma<<<gg, 256, GEMM_SMEM>>>(xh, Wh, be, nullptr, nullptr,
                                     nullptr, eh, el, DIN, 0);
    // q,k,v fused (q: hi/lo; k,v: hi)
    gemm_qkv<<<dim3(12, 32), 256, GEMM_SMEM>>>(eh, Wqh, bq, bk, bv, qh, ql, kh, vh);
    // attention -> ctx (fp16 hi)
    attn_mma<<<dim3(SEQ / 128, 32), 256, AT_SMEM>>>(qh, ql, kh, vh, ch);
    // mha = (eh+el) + ctx @ W0 + b0  (hi/lo out)
    gemm_mma<<<gg, 256, GEMM_SMEM>>>(ch, W0h, b0, eh, el,
                                     nullptr, mh, ml, DMODEL, 0);
    // h1 = relu(mha @ W1 + b1)  (hi only)
    gemm_mma<<<gg, 256, GEMM_SMEM>>>(mh, W1h, b1, nullptr, nullptr,
                                     nullptr, hh, nullptr, DMODEL, 1);
    // out = (mh+ml) + h1 @ W2 + b2  (fp32)
    gemm_mma<<<gg, 256, GEMM_SMEM>>>(hh, W2h, b2, mh, ml,
                                     out, nullptr, nullptr, DMODEL, 0);
}